// round 1
// baseline (speedup 1.0000x reference)
#include <cuda_runtime.h>
#include <math.h>

#define B_   2
#define T_   2048
#define D_   1024
#define H_   16
#define W_   16
#define E_   8
#define HD_  64
#define KCONV (D_*W_)     // 16384
#define BT_   (B_*T_)     // 4096

// ---------------- scratch (device globals; no allocations allowed) ----------
__device__ float  g_xt    [B_*D_*T_];        // x transposed  [b][d][t]     16MB
__device__ float  g_wq_t  [KCONV*D_];        // q_w^T [k=i*16+w][o]         64MB
__device__ float  g_wk_t  [KCONV*D_];        //                             64MB
__device__ float  g_vwt   [D_*D_];           // v_w^T [d][o]                 4MB
__device__ float  g_pwt   [D_*D_];           // p_w^T [d][o]                 4MB
__device__ float  g_qk    [BT_*2*D_];        // [bt][0:1024]=q  [1024:2048]=k 32MB
__device__ float  g_v     [BT_*D_];          // [bt][d]                     16MB
__device__ float  g_attn_t[B_*D_*T_];        // attention out, K-major      16MB
__device__ float  g_scores[B_*H_*E_*T_];     //                              2MB
__device__ float2 g_stats [B_*H_*E_];        // (max, denom) per (b,h,e)

// ---------------- generic 32x32 tiled transpose: dst[c][r] = src[r][c] -----
__global__ void transpose_mat(float* __restrict__ dst, const float* __restrict__ src,
                              int R, int C) {
    __shared__ float tile[32][33];
    int c0 = blockIdx.x * 32, r0 = blockIdx.y * 32;
    #pragma unroll
    for (int j = 0; j < 32; j += 8) {
        tile[threadIdx.y + j][threadIdx.x] =
            src[(size_t)(r0 + threadIdx.y + j) * C + c0 + threadIdx.x];
    }
    __syncthreads();
    #pragma unroll
    for (int j = 0; j < 32; j += 8) {
        dst[(size_t)(c0 + threadIdx.y + j) * R + r0 + threadIdx.x] =
            tile[threadIdx.x][threadIdx.y + j];
    }
}

// ---------------- conv-as-GEMM: qk[m][n] = sum_k x_patch[m][k] * W[k][n] + b -
// m = b*T + t   (4096),  n = o (q: 0..1023) or 1024+o (k),  k = i*16 + w (16384)
// A[m][k] = x[b][t-15+w][i] = x_t[b][i][t-15+w]   (0 if t-15+w < 0)
__global__ __launch_bounds__(256) void conv_gemm(
    float* __restrict__ qkout, const float* __restrict__ xt,
    const float* __restrict__ wqt, const float* __restrict__ wkt,
    const float* __restrict__ qb,  const float* __restrict__ kb)
{
    __shared__ float As[16][128];
    __shared__ float Bs[16][128];
    const int m0  = blockIdx.y * 128;
    const int n0g = blockIdx.x * 128;
    const int b   = m0 >> 11;          // /2048
    const int t0  = m0 & (T_ - 1);
    const float* wt; const float* bias; int n0;
    if (n0g < 1024) { wt = wqt; bias = qb; n0 = n0g; }
    else            { wt = wkt; bias = kb; n0 = n0g - 1024; }
    const float* xb = xt + (size_t)b * D_ * T_;

    const int tid = threadIdx.x;
    const int lr = tid & 127, lw = tid >> 7;   // loader: col / row-pair
    const int tx = tid & 15,  ty = tid >> 4;   // compute 16x16 layout

    float acc[8][8];
    #pragma unroll
    for (int u = 0; u < 8; u++)
        #pragma unroll
        for (int v = 0; v < 8; v++) acc[u][v] = 0.f;

    for (int i = 0; i < D_; i++) {             // one input channel per K-chunk
        const float* xrow = xb + (size_t)i * T_ + t0 - 15;
        #pragma unroll
        for (int j = 0; j < 8; j++) {
            int w  = lw + j * 2;
            int tt = t0 + lr - 15 + w;
            As[w][lr] = (tt >= 0) ? xrow[lr + w] : 0.f;
        }
        const float* wrow = wt + (size_t)i * 16 * D_ + n0;
        #pragma unroll
        for (int j = 0; j < 8; j++) {
            int w = lw + j * 2;
            Bs[w][lr] = wrow[(size_t)w * D_ + lr];
        }
        __syncthreads();
        #pragma unroll
        for (int kk = 0; kk < 16; kk++) {
            float4 a0 = *(const float4*)(&As[kk][ty * 4]);
            float4 a1 = *(const float4*)(&As[kk][64 + ty * 4]);
            float4 b0 = *(const float4*)(&Bs[kk][tx * 4]);
            float4 b1 = *(const float4*)(&Bs[kk][64 + tx * 4]);
            float av[8] = {a0.x,a0.y,a0.z,a0.w,a1.x,a1.y,a1.z,a1.w};
            float bv[8] = {b0.x,b0.y,b0.z,b0.w,b1.x,b1.y,b1.z,b1.w};
            #pragma unroll
            for (int u = 0; u < 8; u++)
                #pragma unroll
                for (int v = 0; v < 8; v++) acc[u][v] += av[u] * bv[v];
        }
        __syncthreads();
    }
    #pragma unroll
    for (int u = 0; u < 8; u++) {
        int mr = (u < 4) ? ty * 4 + u : 64 + ty * 4 + (u - 4);
        float* crow = qkout + (size_t)(m0 + mr) * 2048 + n0g;
        #pragma unroll
        for (int v = 0; v < 8; v++) {
            int c = (v < 4) ? tx * 4 + v : 64 + tx * 4 + (v - 4);
            crow[c] = acc[u][v] + bias[n0 + c];
        }
    }
}

// ---------------- plain GEMM, A given K-major per batch: At[b][K][T] --------
// C[b*T + t][n] = sum_k At[b][k][t] * Bt[k][n] + bias[n]
__global__ __launch_bounds__(256) void gemm_bias(
    float* __restrict__ C, const float* __restrict__ At,
    const float* __restrict__ Bt, const float* __restrict__ bias,
    int K, int N)
{
    __shared__ float As[16][128];
    __shared__ float Bs[16][128];
    const int m0 = blockIdx.y * 128;
    const int n0 = blockIdx.x * 128;
    const int b  = m0 >> 11;
    const int t0 = m0 & (T_ - 1);
    const float* ab = At + (size_t)b * K * T_;

    const int tid = threadIdx.x;
    const int lr = tid & 127, lw = tid >> 7;
    const int tx = tid & 15,  ty = tid >> 4;

    float acc[8][8];
    #pragma unroll
    for (int u = 0; u < 8; u++)
        #pragma unroll
        for (int v = 0; v < 8; v++) acc[u][v] = 0.f;

    for (int k0 = 0; k0 < K; k0 += 16) {
        #pragma unroll
        for (int j = 0; j < 8; j++) {
            int kk = lw + j * 2;
            As[kk][lr] = ab[(size_t)(k0 + kk) * T_ + t0 + lr];
            Bs[kk][lr] = Bt[(size_t)(k0 + kk) * N + n0 + lr];
        }
        __syncthreads();
        #pragma unroll
        for (int kk = 0; kk < 16; kk++) {
            float4 a0 = *(const float4*)(&As[kk][ty * 4]);
            float4 a1 = *(const float4*)(&As[kk][64 + ty * 4]);
            float4 b0 = *(const float4*)(&Bs[kk][tx * 4]);
            float4 b1 = *(const float4*)(&Bs[kk][64 + tx * 4]);
            float av[8] = {a0.x,a0.y,a0.z,a0.w,a1.x,a1.y,a1.z,a1.w};
            float bv[8] = {b0.x,b0.y,b0.z,b0.w,b1.x,b1.y,b1.z,b1.w};
            #pragma unroll
            for (int u = 0; u < 8; u++)
                #pragma unroll
                for (int v = 0; v < 8; v++) acc[u][v] += av[u] * bv[v];
        }
        __syncthreads();
    }
    #pragma unroll
    for (int u = 0; u < 8; u++) {
        int mr = (u < 4) ? ty * 4 + u : 64 + ty * 4 + (u - 4);
        float* crow = C + (size_t)(m0 + mr) * N + n0;
        #pragma unroll
        for (int v = 0; v < 8; v++) {
            int c = (v < 4) ? tx * 4 + v : 64 + tx * 4 + (v - 4);
            crow[c] = acc[u][v] + bias[n0 + c];
        }
    }
}

// ---------------- log-sparse scores: score[b,h,e,t] = q[t].k[(t+2^e)%T]*scale
__global__ __launch_bounds__(256) void e1_scores(
    const float* __restrict__ qk, float* __restrict__ scores)
{
    int lane = threadIdx.x & 31, wid = threadIdx.x >> 5;
    int gw = blockIdx.x * 8 + wid;             // 0..65535 = (b,h,t)
    int t = gw & (T_ - 1);
    int h = (gw >> 11) & 15;
    int b = gw >> 15;
    const float* qrow = qk + (size_t)(b * T_ + t) * 2048 + h * 64;
    float q0 = qrow[lane], q1 = qrow[lane + 32];
    #pragma unroll
    for (int e = 0; e < 8; e++) {
        int ts = (t + (1 << e)) & (T_ - 1);
        const float* kr = qk + (size_t)(b * T_ + ts) * 2048 + 1024 + h * 64;
        float s = q0 * kr[lane] + q1 * kr[lane + 32];
        #pragma unroll
        for (int o = 16; o; o >>= 1) s += __shfl_xor_sync(0xffffffffu, s, o);
        if (lane == 0)
            scores[((size_t)((b * 16 + h) * 8 + e)) * T_ + t] = s * 0.125f;
    }
}

// ---------------- softmax stats over T per (b,h,e) --------------------------
__global__ void e2_stats(const float* __restrict__ scores, float2* __restrict__ stats)
{
    __shared__ float red[256];
    int idx = blockIdx.x;
    const float* s = scores + (size_t)idx * T_;
    int tid = threadIdx.x;
    float m = -1e30f;
    for (int i = tid; i < T_; i += 256) m = fmaxf(m, s[i]);
    red[tid] = m; __syncthreads();
    for (int o = 128; o > 0; o >>= 1) {
        if (tid < o) red[tid] = fmaxf(red[tid], red[tid + o]);
        __syncthreads();
    }
    float mt = red[0]; __syncthreads();
    float sm = 0.f;
    for (int i = tid; i < T_; i += 256) sm += expf(s[i] - mt);
    red[tid] = sm; __syncthreads();
    for (int o = 128; o > 0; o >>= 1) {
        if (tid < o) red[tid] += red[tid + o];
        __syncthreads();
    }
    if (tid == 0) stats[idx] = make_float2(mt, red[0]);
}

// ---------------- local window attention + log-sparse accumulation ----------
// one warp per (b,h,t); writes attn output K-major: attn_t[b][d][t]
__global__ __launch_bounds__(256) void attn_kernel(
    const float* __restrict__ qk, const float* __restrict__ vbuf,
    const float* __restrict__ scores, const float2* __restrict__ stats,
    float* __restrict__ attn_t)
{
    __shared__ float st[8][65];
    int lane = threadIdx.x & 31, wid = threadIdx.x >> 5;
    int tc = blockIdx.x & 255;
    int h  = (blockIdx.x >> 8) & 15;
    int b  = blockIdx.x >> 12;
    int t  = tc * 8 + wid;

    const float* qrow = qk + (size_t)(b * T_ + t) * 2048 + h * 64;
    float q0 = qrow[lane], q1 = qrow[lane + 32];

    // local window scores (exactly 0 for padded positions, matching reference)
    float sw[16];
    #pragma unroll
    for (int w = 0; w < 16; w++) {
        int tt = t - 15 + w;
        float s = 0.f;
        if (tt >= 0) {
            const float* kr = qk + (size_t)(b * T_ + tt) * 2048 + 1024 + h * 64;
            s = q0 * kr[lane] + q1 * kr[lane + 32];
            #pragma unroll
            for (int o = 16; o; o >>= 1) s += __shfl_xor_sync(0xffffffffu, s, o);
            s *= 0.125f;
        }
        sw[w] = s;
    }
    float m = sw[0];
    #pragma unroll
    for (int w = 1; w < 16; w++) m = fmaxf(m, sw[w]);
    float den = 0.f;
    #pragma unroll
    for (int w = 0; w < 16; w++) den += expf(sw[w] - m);
    float inv = 1.f / den;

    float a0 = 0.f, a1 = 0.f;
    #pragma unroll
    for (int w = 0; w < 16; w++) {
        int tt = t - 15 + w;
        if (tt >= 0) {
            float al = expf(sw[w] - m) * inv;
            const float* vr = vbuf + (size_t)(b * T_ + tt) * 1024 + h * 64;
            a0 += al * vr[lane];
            a1 += al * vr[lane + 32];
        }
    }
    // log-sparse terms
    const float* sc = scores + ((size_t)((b * 16 + h) * 8)) * T_ + t;
    #pragma unroll
    for (int e = 0; e < 8; e++) {
        float2 stv = stats[(b * 16 + h) * 8 + e];
        float al = expf(sc[(size_t)e * T_] - stv.x) / stv.y;
        int ts = (t + (1 << e)) & (T_ - 1);
        const float* vr = vbuf + (size_t)(b * T_ + ts) * 1024 + h * 64;
        a0 += al * vr[lane];
        a1 += al * vr[lane + 32];
    }
    st[wid][lane]      = a0;
    st[wid][lane + 32] = a1;
    __syncthreads();
    for (int idx = threadIdx.x; idx < 512; idx += 256) {
        int d = idx >> 3, tt = idx & 7;
        attn_t[((size_t)(b * 1024 + h * 64 + d)) * T_ + tc * 8 + tt] = st[tt][d];
    }
}

// ---------------- launch --------------------------------------------------
extern "C" void kernel_launch(void* const* d_in, const int* in_sizes, int n_in,
                              void* d_out, int out_size)
{
    const float* x   = (const float*)d_in[0];
    const float* q_w = (const float*)d_in[1];
    const float* q_b = (const float*)d_in[2];
    const float* k_w = (const float*)d_in[3];
    const float* k_b = (const float*)d_in[4];
    const float* v_w = (const float*)d_in[5];
    const float* v_b = (const float*)d_in[6];
    const float* p_w = (const float*)d_in[7];
    const float* p_b = (const float*)d_in[8];
    (void)in_sizes; (void)n_in; (void)out_size;

    float *xt, *wqt, *wkt, *vwt, *pwt, *qk, *vbuf, *attn_t, *scores;
    float2* stats;
    cudaGetSymbolAddress((void**)&xt,     g_xt);
    cudaGetSymbolAddress((void**)&wqt,    g_wq_t);
    cudaGetSymbolAddress((void**)&wkt,    g_wk_t);
    cudaGetSymbolAddress((void**)&vwt,    g_vwt);
    cudaGetSymbolAddress((void**)&pwt,    g_pwt);
    cudaGetSymbolAddress((void**)&qk,     g_qk);
    cudaGetSymbolAddress((void**)&vbuf,   g_v);
    cudaGetSymbolAddress((void**)&attn_t, g_attn_t);
    cudaGetSymbolAddress((void**)&scores, g_scores);
    cudaGetSymbolAddress((void**)&stats,  g_stats);

    dim3 tb(32, 8);
    // weight / activation repacking (all-coalesced GEMM operands)
    transpose_mat<<<dim3(KCONV/32, D_/32), tb>>>(wqt, q_w, D_, KCONV);
    transpose_mat<<<dim3(KCONV/32, D_/32), tb>>>(wkt, k_w, D_, KCONV);
    transpose_mat<<<dim3(D_/32, D_/32),    tb>>>(vwt, v_w, D_, D_);
    transpose_mat<<<dim3(D_/32, D_/32),    tb>>>(pwt, p_w, D_, D_);
    transpose_mat<<<dim3(D_/32, T_/32),    tb>>>(xt,            x,           T_, D_);
    transpose_mat<<<dim3(D_/32, T_/32),    tb>>>(xt + D_ * T_,  x + T_ * D_, T_, D_);

    // fused q+k causal conv as one big implicit-im2col GEMM
    conv_gemm<<<dim3(2 * D_ / 128, BT_ / 128), 256>>>(qk, xt, wqt, wkt, q_b, k_b);
    // v projection
    gemm_bias<<<dim3(D_ / 128, BT_ / 128), 256>>>(vbuf, xt, vwt, v_b, D_, D_);
    // log-sparse scores + global softmax stats
    e1_scores<<<B_ * H_ * T_ / 8, 256>>>(qk, scores);
    e2_stats<<<B_ * H_ * E_, 256>>>(scores, stats);
    // local + log-sparse attention, K-major output
    attn_kernel<<<B_ * H_ * T_ / 8, 256>>>(qk, vbuf, scores, stats, attn_t);
    // output projection -> d_out
    gemm_bias<<<dim3(D_ / 128, BT_ / 128), 256>>>((float*)d_out, attn_t, pwt, p_b, D_, D_);
}

// round 2
// speedup vs baseline: 1.3822x; 1.3822x over previous
#include <cuda_runtime.h>
#include <math.h>

#define B_   2
#define T_   2048
#define D_   1024
#define H_   16
#define W_   16
#define E_   8
#define KCONV (D_*W_)     // 16384
#define BT_   (B_*T_)     // 4096
#define SROW  136         // padded smem row (floats): conflict-free frag LDS

// ---------------- scratch (device globals; no allocations allowed) ----------
__device__ float  g_xt    [B_*D_*T_];        // x transposed  [b][d][t]      16MB
__device__ float  g_xim   [(size_t)B_*KCONV*T_]; // im2col [b][i*16+w][t]   256MB
__device__ float  g_wqk   [(size_t)KCONV*2*D_];  // [k][ q(0:1024) | k(1024:2048) ] 128MB
__device__ float  g_vwt   [D_*D_];           // v_w^T [d][o]                  4MB
__device__ float  g_pwt   [D_*D_];           // p_w^T [d][o]                  4MB
__device__ float  g_qkb   [2*D_];            // concat bias
__device__ float  g_qk    [BT_*2*D_];        // [bt][0:1024]=q [1024:2048]=k 32MB
__device__ float  g_v     [BT_*D_];          // [bt][d]                      16MB
__device__ float  g_attn  [B_*D_*T_];        // attention out, K-major       16MB
__device__ float  g_scores[B_*H_*E_*T_];     //                               2MB
__device__ float2 g_stats [B_*H_*E_];        // (max, denom) per (b,h,e)

// ---------------- 32x32 tiled transpose with dst stride / column offset ----
// dst[(c)*dstride + coloff + r] = src[r*C + c]
__global__ void transpose_mat(float* __restrict__ dst, const float* __restrict__ src,
                              int R, int C, int dstride, int coloff) {
    __shared__ float tile[32][33];
    int c0 = blockIdx.x * 32, r0 = blockIdx.y * 32;
    #pragma unroll
    for (int j = 0; j < 32; j += 8)
        tile[threadIdx.y + j][threadIdx.x] =
            src[(size_t)(r0 + threadIdx.y + j) * C + c0 + threadIdx.x];
    __syncthreads();
    #pragma unroll
    for (int j = 0; j < 32; j += 8)
        dst[(size_t)(c0 + threadIdx.y + j) * dstride + coloff + r0 + threadIdx.x] =
            tile[threadIdx.x][threadIdx.y + j];
}

// ---------------- im2col expand: xim[b][c*16+w][t] = xt[b][c][t-15+w] | 0 ---
__global__ __launch_bounds__(256) void expand_im2col(
    float* __restrict__ xim, const float* __restrict__ xt)
{
    size_t idx = ((size_t)blockIdx.x * 256 + threadIdx.x) * 4;
    int t  = idx & (T_ - 1);
    int w  = (idx >> 11) & 15;
    size_t cd = idx >> 15;               // b*D + c
    const float* src = xt + cd * T_ + t - 15 + w;
    float4 v;
    int ts = t - 15 + w;
    v.x = (ts + 0 >= 0) ? src[0] : 0.f;
    v.y = (ts + 1 >= 0) ? src[1] : 0.f;
    v.z = (ts + 2 >= 0) ? src[2] : 0.f;
    v.w = (ts + 3 >= 0) ? src[3] : 0.f;
    *(float4*)(xim + idx) = v;
}

__global__ void concat_bias(float* __restrict__ d, const float* __restrict__ qb,
                            const float* __restrict__ kb) {
    int i = blockIdx.x * 256 + threadIdx.x;
    d[i] = (i < D_) ? qb[i] : kb[i - D_];
}

// ---------------- tf32x3 GEMM core ----------------------------------------
__device__ __forceinline__ unsigned f2tf(float x) {
    unsigned u; asm("cvt.rna.tf32.f32 %0, %1;" : "=r"(u) : "f"(x)); return u;
}
__device__ __forceinline__ void mma8(float* c, const unsigned* a, const unsigned* b) {
    asm volatile("mma.sync.aligned.m16n8k8.row.col.f32.tf32.tf32.f32 "
        "{%0,%1,%2,%3},{%4,%5,%6,%7},{%8,%9},{%0,%1,%2,%3};\n"
        : "+f"(c[0]), "+f"(c[1]), "+f"(c[2]), "+f"(c[3])
        : "r"(a[0]), "r"(a[1]), "r"(a[2]), "r"(a[3]), "r"(b[0]), "r"(b[1]));
}

// C[b*T+t][n] = sum_k At[b*abatch + k*T_ + t] * Bt[k*N + n] + bias[n]
// grid: (N/128, 4096/128), 256 threads, warp grid 2(m) x 4(n), warp tile 64x32
__global__ __launch_bounds__(256, 2) void gemm_tf32(
    float* __restrict__ C, const float* __restrict__ At, const float* __restrict__ Bt,
    const float* __restrict__ bias, int K, int N, long abatch)
{
    extern __shared__ float smf[];
    float* As = smf;                    // [2][32][SROW]
    float* Bs = smf + 2 * 32 * SROW;
    const int m0 = blockIdx.y * 128, n0 = blockIdx.x * 128;
    const int b  = m0 >> 11, t0 = m0 & (T_ - 1);
    const float* Ab = At + (long)b * abatch + t0;
    const float* Bb = Bt + n0;
    const int tid = threadIdx.x, lane = tid & 31, warp = tid >> 5;
    const int mb = (warp >> 2) * 64, nb = (warp & 3) * 32;
    const int gr = lane >> 2, ctl = lane & 3;

    float acc[16][4];
    #pragma unroll
    for (int i = 0; i < 16; i++)
        #pragma unroll
        for (int j = 0; j < 4; j++) acc[i][j] = 0.f;

    auto load_stage = [&](int s, int buf) {
        const float* a = Ab + (long)s * 32 * T_;
        const float* bsrc = Bb + (long)s * 32 * N;
        float* Ad = As + buf * 32 * SROW;
        float* Bd = Bs + buf * 32 * SROW;
        #pragma unroll
        for (int j = 0; j < 4; j++) {
            int idx = tid + j * 256;
            int k = idx >> 5, seg = (idx & 31) * 4;
            unsigned da = (unsigned)__cvta_generic_to_shared(Ad + k * SROW + seg);
            asm volatile("cp.async.cg.shared.global [%0], [%1], 16;\n"
                         :: "r"(da), "l"(a + (long)k * T_ + seg));
            unsigned db = (unsigned)__cvta_generic_to_shared(Bd + k * SROW + seg);
            asm volatile("cp.async.cg.shared.global [%0], [%1], 16;\n"
                         :: "r"(db), "l"(bsrc + (long)k * N + seg));
        }
        asm volatile("cp.async.commit_group;\n");
    };

    const int ns = K / 32;
    load_stage(0, 0);
    for (int s = 0; s < ns; s++) {
        const int buf = s & 1;
        if (s + 1 < ns) {
            load_stage(s + 1, buf ^ 1);
            asm volatile("cp.async.wait_group 1;\n");
        } else {
            asm volatile("cp.async.wait_group 0;\n");
        }
        __syncthreads();
        const float* Asb = As + buf * 32 * SROW;
        const float* Bsb = Bs + buf * 32 * SROW;
        #pragma unroll
        for (int ks = 0; ks < 4; ks++) {
            unsigned bh[8], bl[8];
            #pragma unroll
            for (int nt = 0; nt < 4; nt++)
                #pragma unroll
                for (int r = 0; r < 2; r++) {
                    float v = Bsb[(ks * 8 + ctl + r * 4) * SROW + nb + nt * 8 + gr];
                    unsigned h = f2tf(v);
                    bh[nt * 2 + r] = h;
                    bl[nt * 2 + r] = f2tf(v - __uint_as_float(h));
                }
            #pragma unroll
            for (int mt = 0; mt < 4; mt++) {
                unsigned ah[4], al[4];
                #pragma unroll
                for (int r = 0; r < 4; r++) {
                    int kk = ks * 8 + ctl + (r >> 1) * 4;
                    int mm = mb + mt * 16 + gr + (r & 1) * 8;
                    float v = Asb[kk * SROW + mm];
                    unsigned h = f2tf(v);
                    ah[r] = h;
                    al[r] = f2tf(v - __uint_as_float(h));
                }
                #pragma unroll
                for (int nt = 0; nt < 4; nt++) {
                    mma8(acc[mt * 4 + nt], ah, bh + nt * 2);
                    mma8(acc[mt * 4 + nt], ah, bl + nt * 2);
                    mma8(acc[mt * 4 + nt], al, bh + nt * 2);
                }
            }
        }
        __syncthreads();
    }
    #pragma unroll
    for (int mt = 0; mt < 4; mt++)
        #pragma unroll
        for (int nt = 0; nt < 4; nt++) {
            float* a = acc[mt * 4 + nt];
            int row = m0 + mb + mt * 16 + gr;
            int col = n0 + nb + nt * 8 + ctl * 2;
            float b0 = bias[col], b1 = bias[col + 1];
            float2 v0 = make_float2(a[0] + b0, a[1] + b1);
            float2 v1 = make_float2(a[2] + b0, a[3] + b1);
            *(float2*)&C[(long)row * N + col] = v0;
            *(float2*)&C[(long)(row + 8) * N + col] = v1;
        }
}

// ---------------- log-sparse scores -----------------------------------------
__global__ __launch_bounds__(256) void e1_scores(
    const float* __restrict__ qk, float* __restrict__ scores)
{
    int lane = threadIdx.x & 31, wid = threadIdx.x >> 5;
    int gw = blockIdx.x * 8 + wid;
    int t = gw & (T_ - 1);
    int h = (gw >> 11) & 15;
    int b = gw >> 15;
    const float* qrow = qk + (size_t)(b * T_ + t) * 2048 + h * 64;
    float q0 = qrow[lane], q1 = qrow[lane + 32];
    #pragma unroll
    for (int e = 0; e < 8; e++) {
        int ts = (t + (1 << e)) & (T_ - 1);
        const float* kr = qk + (size_t)(b * T_ + ts) * 2048 + 1024 + h * 64;
        float s = q0 * kr[lane] + q1 * kr[lane + 32];
        #pragma unroll
        for (int o = 16; o; o >>= 1) s += __shfl_xor_sync(0xffffffffu, s, o);
        if (lane == 0)
            scores[((size_t)((b * 16 + h) * 8 + e)) * T_ + t] = s * 0.125f;
    }
}

__global__ void e2_stats(const float* __restrict__ scores, float2* __restrict__ stats)
{
    __shared__ float red[256];
    int idx = blockIdx.x;
    const float* s = scores + (size_t)idx * T_;
    int tid = threadIdx.x;
    float m = -1e30f;
    for (int i = tid; i < T_; i += 256) m = fmaxf(m, s[i]);
    red[tid] = m; __syncthreads();
    for (int o = 128; o > 0; o >>= 1) {
        if (tid < o) red[tid] = fmaxf(red[tid], red[tid + o]);
        __syncthreads();
    }
    float mt = red[0]; __syncthreads();
    float sm = 0.f;
    for (int i = tid; i < T_; i += 256) sm += expf(s[i] - mt);
    red[tid] = sm; __syncthreads();
    for (int o = 128; o > 0; o >>= 1) {
        if (tid < o) red[tid] += red[tid + o];
        __syncthreads();
    }
    if (tid == 0) stats[idx] = make_float2(mt, red[0]);
}

// ---------------- local + log-sparse attention, K-major output --------------
__global__ __launch_bounds__(256) void attn_kernel(
    const float* __restrict__ qk, const float* __restrict__ vbuf,
    const float* __restrict__ scores, const float2* __restrict__ stats,
    float* __restrict__ attn_t)
{
    __shared__ float st[8][65];
    int lane = threadIdx.x & 31, wid = threadIdx.x >> 5;
    int tc = blockIdx.x & 255;
    int h  = (blockIdx.x >> 8) & 15;
    int b  = blockIdx.x >> 12;
    int t  = tc * 8 + wid;

    const float* qrow = qk + (size_t)(b * T_ + t) * 2048 + h * 64;
    float q0 = qrow[lane], q1 = qrow[lane + 32];

    float sw[16];
    #pragma unroll
    for (int w = 0; w < 16; w++) {
        int tt = t - 15 + w;
        float s = 0.f;
        if (tt >= 0) {
            const float* kr = qk + (size_t)(b * T_ + tt) * 2048 + 1024 + h * 64;
            s = q0 * kr[lane] + q1 * kr[lane + 32];
            #pragma unroll
            for (int o = 16; o; o >>= 1) s += __shfl_xor_sync(0xffffffffu, s, o);
            s *= 0.125f;
        }
        sw[w] = s;
    }
    float m = sw[0];
    #pragma unroll
    for (int w = 1; w < 16; w++) m = fmaxf(m, sw[w]);
    float den = 0.f;
    #pragma unroll
    for (int w = 0; w < 16; w++) den += expf(sw[w] - m);
    float inv = 1.f / den;

    float a0 = 0.f, a1 = 0.f;
    #pragma unroll
    for (int w = 0; w < 16; w++) {
        int tt = t - 15 + w;
        if (tt >= 0) {
            float al = expf(sw[w] - m) * inv;
            const float* vr = vbuf + (size_t)(b * T_ + tt) * 1024 + h * 64;
            a0 += al * vr[lane];
            a1 += al * vr[lane + 32];
        }
    }
    const float* sc = scores + ((size_t)((b * 16 + h) * 8)) * T_ + t;
    #pragma unroll
    for (int e = 0; e < 8; e++) {
        float2 stv = stats[(b * 16 + h) * 8 + e];
        float al = expf(sc[(size_t)e * T_] - stv.x) / stv.y;
        int ts = (t + (1 << e)) & (T_ - 1);
        const float* vr = vbuf + (size_t)(b * T_ + ts) * 1024 + h * 64;
        a0 += al * vr[lane];
        a1 += al * vr[lane + 32];
    }
    st[wid][lane]      = a0;
    st[wid][lane + 32] = a1;
    __syncthreads();
    for (int idx = threadIdx.x; idx < 512; idx += 256) {
        int d = idx >> 3, tt = idx & 7;
        attn_t[((size_t)(b * 1024 + h * 64 + d)) * T_ + tc * 8 + tt] = st[tt][d];
    }
}

// ---------------- launch ----------------------------------------------------
extern "C" void kernel_launch(void* const* d_in, const int* in_sizes, int n_in,
                              void* d_out, int out_size)
{
    const float* x   = (const float*)d_in[0];
    const float* q_w = (const float*)d_in[1];
    const float* q_b = (const float*)d_in[2];
    const float* k_w = (const float*)d_in[3];
    const float* k_b = (const float*)d_in[4];
    const float* v_w = (const float*)d_in[5];
    const float* v_b = (const float*)d_in[6];
    const float* p_w = (const float*)d_in[7];
    const float* p_b = (const float*)d_in[8];
    (void)in_sizes; (void)n_in; (void)out_size;

    float *xt, *xim, *wqk, *vwt, *pwt, *qkb, *qk, *vbuf, *attn, *scores;
    float2* stats;
    cudaGetSymbolAddress((void**)&xt,     g_xt);
    cudaGetSymbolAddress((void**)&xim,    g_xim);
    cudaGetSymbolAddress((void**)&wqk,    g_wqk);
    cudaGetSymbolAddress((void**)&vwt,    g_vwt);
    cudaGetSymbolAddress((void**)&pwt,    g_pwt);
    cudaGetSymbolAddress((void**)&qkb,    g_qkb);
    cudaGetSymbolAddress((void**)&qk,     g_qk);
    cudaGetSymbolAddress((void**)&vbuf,   g_v);
    cudaGetSymbolAddress((void**)&attn,   g_attn);
    cudaGetSymbolAddress((void**)&scores, g_scores);
    cudaGetSymbolAddress((void**)&stats,  g_stats);

    const int smemsz = 2 * 2 * 32 * SROW * 4;   // 69632 B
    cudaFuncSetAttribute(gemm_tf32, cudaFuncAttributeMaxDynamicSharedMemorySize, smemsz);

    dim3 tb(32, 8);
    // weight repack: wqk[k][0:1024]=q_w^T, [1024:2048]=k_w^T
    transpose_mat<<<dim3(KCONV/32, D_/32), tb>>>(wqk, q_w, D_, KCONV, 2*D_, 0);
    transpose_mat<<<dim3(KCONV/32, D_/32), tb>>>(wqk, k_w, D_, KCONV, 2*D_, D_);
    transpose_mat<<<dim3(D_/32, D_/32),    tb>>>(vwt, v_w, D_, D_, D_, 0);
    transpose_mat<<<dim3(D_/32, D_/32),    tb>>>(pwt, p_w, D_, D_, D_, 0);
    transpose_mat<<<dim3(D_/32, T_/32),    tb>>>(xt,           x,            T_, D_, T_, 0);
    transpose_mat<<<dim3(D_/32, T_/32),    tb>>>(xt + D_*T_,   x + T_*D_,    T_, D_, T_, 0);
    concat_bias<<<2 * D_ / 256, 256>>>(qkb, q_b, k_b);
    expand_im2col<<<(size_t)B_*KCONV*T_/1024, 256>>>(xim, xt);

    // conv q+k as one GEMM: M=4096, N=2048, K=16384
    gemm_tf32<<<dim3(2*D_/128, BT_/128), 256, smemsz>>>(
        qk, xim, wqk, qkb, KCONV, 2*D_, (long)KCONV*T_);
    // v projection: K=N=1024
    gemm_tf32<<<dim3(D_/128, BT_/128), 256, smemsz>>>(
        vbuf, xt, vwt, v_b, D_, D_, (long)D_*T_);
    // attention
    e1_scores<<<B_*H_*T_/8, 256>>>(qk, scores);
    e2_stats<<<B_*H_*E_, 256>>>(scores, stats);
    attn_kernel<<<B_*H_*T_/8, 256>>>(qk, vbuf, scores, stats, attn);
    // output projection
    gemm_tf32<<<dim3(D_/128, BT_/128), 256, smemsz>>>(
        (float*)d_out, attn, pwt, p_b, D_, D_, (long)D_*T_);
}

// round 8
// speedup vs baseline: 2.2107x; 1.5994x over previous
#include <cuda_runtime.h>
#include <cuda_fp16.h>
#include <math.h>
#include <stdint.h>

#define B_   2
#define T_   2048
#define D_   1024
#define H_   16
#define W_   16
#define E_   8
#define BT_  (B_*T_)
#define TPAD (T_+16)

#define MT 128
#define NT 128
#define RPAD 40                  // smem row stride in halves (80 bytes)
#define PLANE_B (128*RPAD*2)     // 10240 bytes per 128x32 fp16 plane
#define STAGE_B (4*PLANE_B)      // Ah, Am, Bh, Bm
#define SMEM_TOTAL (2*STAGE_B)   // 81920

// ---------------- device scratch -------------------------------------------
__device__ uint4 g_xh_  [B_*TPAD*D_/8];          // x fp16 hi plane (15-row zero pad)
__device__ uint4 g_xm_  [B_*TPAD*D_/8];
__device__ uint4 g_wqkh_[(size_t)W_*2*D_*D_/8];  // [w][n(q|k)][i] hi
__device__ uint4 g_wqkm_[(size_t)W_*2*D_*D_/8];
__device__ uint4 g_wvh_ [D_*D_/8];
__device__ uint4 g_wvm_ [D_*D_/8];
__device__ uint4 g_wph_ [D_*D_/8];
__device__ uint4 g_wpm_ [D_*D_/8];
__device__ uint4 g_ah_  [B_*TPAD*D_/8];          // attn out planes (padded)
__device__ uint4 g_am_  [B_*TPAD*D_/8];
__device__ float g_qk   [BT_*2*D_];
__device__ float g_v    [BT_*D_];
__device__ float g_qkb  [2*D_];
__device__ float g_scores[B_*H_*E_*T_];
__device__ float2 g_stats[B_*H_*E_];

// ---------------- helpers ---------------------------------------------------
__device__ __forceinline__ uint32_t smem_u32(const void* p) {
    uint32_t a;
    asm("{ .reg .u64 t; cvta.to.shared.u64 t, %1; cvt.u32.u64 %0, t; }" : "=r"(a) : "l"(p));
    return a;
}
__device__ __forceinline__ void ldsm4(uint32_t* r, uint32_t a) {
    asm volatile("ldmatrix.sync.aligned.m8n8.x4.shared.b16 {%0,%1,%2,%3}, [%4];"
                 : "=r"(r[0]), "=r"(r[1]), "=r"(r[2]), "=r"(r[3]) : "r"(a));
}
__device__ __forceinline__ void mma16(float* c, const uint32_t* a, const uint32_t* b) {
    asm volatile("mma.sync.aligned.m16n8k16.row.col.f32.f16.f16.f32 "
        "{%0,%1,%2,%3},{%4,%5,%6,%7},{%8,%9},{%0,%1,%2,%3};\n"
        : "+f"(c[0]), "+f"(c[1]), "+f"(c[2]), "+f"(c[3])
        : "r"(a[0]), "r"(a[1]), "r"(a[2]), "r"(a[3]), "r"(b[0]), "r"(b[1]));
}
#define CP16(dst, src) asm volatile("cp.async.cg.shared.global [%0], [%1], 16;" \
    :: "r"(dst), "l"(src))

// ---------------- prep kernels ---------------------------------------------
__global__ __launch_bounds__(256) void split_x(
    __half* __restrict__ xh, __half* __restrict__ xm, const float* __restrict__ x)
{
    size_t idx = (size_t)blockIdx.x * 256 + threadIdx.x;   // over B*TPAD*D
    int d = idx & (D_ - 1);
    int p = (idx >> 10) % TPAD;
    int b = (int)(idx / ((size_t)TPAD * D_));
    float v = 0.f;
    int t = p - 15;
    if (t >= 0 && t < T_) v = x[((size_t)b * T_ + t) * D_ + d];
    __half h = __float2half(v);
    xh[idx] = h;
    xm[idx] = __float2half(v - __half2float(h));
}

__global__ __launch_bounds__(256) void split_wqk(
    __half* __restrict__ oh, __half* __restrict__ om,
    const float* __restrict__ qw, const float* __restrict__ kw)
{
    size_t idx = (size_t)blockIdx.x * 256 + threadIdx.x;   // (n,i) over 2048*1024
    int i = idx & (D_ - 1);
    int n = (int)(idx >> 10);
    const float* src = (n < D_) ? (qw + ((size_t)n * D_ + i) * W_)
                                : (kw + ((size_t)(n - D_) * D_ + i) * W_);
    #pragma unroll
    for (int w = 0; w < W_; w++) {
        float v = src[w];
        __half h = __float2half(v);
        size_t o = ((size_t)w * 2 * D_ + n) * D_ + i;
        oh[o] = h;
        om[o] = __float2half(v - __half2float(h));
    }
}

__global__ __launch_bounds__(256) void split_w1(
    __half* __restrict__ oh, __half* __restrict__ om, const float* __restrict__ w)
{
    size_t idx = (size_t)blockIdx.x * 256 + threadIdx.x;
    float v = w[idx];
    __half h = __float2half(v);
    oh[idx] = h;
    om[idx] = __float2half(v - __half2float(h));
}

__global__ void zero_apad(__half* __restrict__ ah, __half* __restrict__ am) {
    int idx = blockIdx.x * 256 + threadIdx.x;              // B*16*D (pad rows + last)
    int d = idx & (D_ - 1), p = (idx >> 10) % 16, b = idx / (16 * D_);
    int row = (p < 15) ? p : (TPAD - 1);
    size_t o = ((size_t)b * TPAD + row) * D_ + d;
    ah[o] = __float2half(0.f);
    am[o] = __float2half(0.f);
}

__global__ void concat_bias(float* __restrict__ d, const float* __restrict__ qb,
                            const float* __restrict__ kb) {
    int i = blockIdx.x * 256 + threadIdx.x;
    d[i] = (i < D_) ? qb[i] : kb[i - D_];
}

// ---------------- HMMA GEMM -------------------------------------------------
// C[b*T+t][n] = sum_{w<wcount} sum_k A[b*TPAD + t0+m+wbase+w][k] * Bp[w][n][k] + bias[n]
__global__ __launch_bounds__(256, 1) void gemm_hmma(
    float* __restrict__ C,
    const __half* __restrict__ Ah, const __half* __restrict__ Am,
    const __half* __restrict__ Bh, const __half* __restrict__ Bm,
    const float* __restrict__ bias, int Ntot, int wcount, int wbase)
{
    extern __shared__ __align__(1024) char smem[];
    const uint32_t sb = smem_u32(smem);
    const int tid = threadIdx.x, warp = tid >> 5, lane = tid & 31;
    const int wm = warp >> 2, wn = warp & 3;       // warp grid 2x4, tile 64x32
    const int m0 = blockIdx.y * MT, n0 = blockIdx.x * NT;
    const int b = m0 >> 11, t0 = m0 & (T_ - 1);
    const size_t arow0 = (size_t)b * TPAD + t0 + wbase;

    const int kt = D_ / 32;                        // 32 k-chunks per w-phase
    const int ns = wcount * kt;

    auto load_stage = [&](int s, int buf) {
        const int w = s / kt, k0 = (s % kt) * 32;  // k0 in halves
        const uint32_t st = sb + buf * STAGE_B;
        #pragma unroll
        for (int j = 0; j < 8; j++) {
            int idx = tid + j * 256;               // 2048 16B chunks
            int c   = idx & 3;                     // 16B chunk within row
            int row = (idx >> 2) & 127;
            int pl  = (idx >> 9) & 1;
            if (idx < 1024) {
                const __half* src = (pl ? Am : Ah) + (arow0 + w + row) * D_ + k0 + c * 8;
                CP16(st + pl * PLANE_B + row * 80 + c * 16, src);
            } else {
                const __half* src = (pl ? Bm : Bh)
                    + ((size_t)w * Ntot + n0 + row) * (size_t)D_ + k0 + c * 8;
                CP16(st + 2 * PLANE_B + pl * PLANE_B + row * 80 + c * 16, src);
            }
        }
        asm volatile("cp.async.commit_group;");
    };

    float acc[4][4][4];
    #pragma unroll
    for (int i = 0; i < 4; i++)
        #pragma unroll
        for (int j = 0; j < 4; j++)
            #pragma unroll
            for (int q = 0; q < 4; q++) acc[i][j][q] = 0.f;

    const int la = lane & 7, g1 = (lane >> 3) & 1, g2 = lane >> 4;
    // A x4 lane address components: row = mt*16 + g1*8 + la ; col = kh*32 + g2*16
    // B x4 lane address components: row = ntp*16 + g2*8 + la ; col = kh*32 + g1*16
    const int arow_l = wm * 64 + g1 * 8 + la;
    const int brow_l = wn * 32 + g2 * 8 + la;

    load_stage(0, 0);
    for (int s = 0; s < ns; s++) {
        const int buf = s & 1;
        if (s + 1 < ns) {
            load_stage(s + 1, buf ^ 1);
            asm volatile("cp.async.wait_group 1;" ::: "memory");
        } else {
            asm volatile("cp.async.wait_group 0;" ::: "memory");
        }
        __syncthreads();
        const uint32_t st  = sb + buf * STAGE_B;
        const uint32_t Abh = st;
        const uint32_t Abm = st + PLANE_B;
        const uint32_t Bbh = st + 2 * PLANE_B;
        const uint32_t Bbm = st + 3 * PLANE_B;
        #pragma unroll
        for (int kh = 0; kh < 2; kh++) {
            const int acol = kh * 32 + g2 * 16;
            const int bcol = kh * 32 + g1 * 16;
            uint32_t ah[4][4], am[4][4];
            #pragma unroll
            for (int mt = 0; mt < 4; mt++) {
                uint32_t off = (arow_l + mt * 16) * 80 + acol;
                ldsm4(ah[mt], Abh + off);
                ldsm4(am[mt], Abm + off);
            }
            #pragma unroll
            for (int ntp = 0; ntp < 2; ntp++) {
                uint32_t boff = (brow_l + ntp * 16) * 80 + bcol;
                uint32_t bh[4], bm[4];
                ldsm4(bh, Bbh + boff);
                ldsm4(bm, Bbm + boff);
                #pragma unroll
                for (int mt = 0; mt < 4; mt++) {
                    #pragma unroll
                    for (int hn = 0; hn < 2; hn++) {
                        float* a = acc[mt][ntp * 2 + hn];
                        mma16(a, ah[mt], bh + 2 * hn);
                        mma16(a, ah[mt], bm + 2 * hn);
                        mma16(a, am[mt], bh + 2 * hn);
                    }
                }
            }
        }
        __syncthreads();
    }

    // epilogue
    const int er = lane >> 2, ec = (lane & 3) * 2;
    #pragma unroll
    for (int mt = 0; mt < 4; mt++) {
        int row = m0 + wm * 64 + mt * 16 + er;
        #pragma unroll
        for (int nt = 0; nt < 4; nt++) {
            int col = n0 + wn * 32 + nt * 8 + ec;
            float b0 = bias[col], b1 = bias[col + 1];
            float* a = acc[mt][nt];
            *(float2*)&C[(size_t)row * Ntot + col] = make_float2(a[0] + b0, a[1] + b1);
            *(float2*)&C[(size_t)(row + 8) * Ntot + col] = make_float2(a[2] + b0, a[3] + b1);
        }
    }
}

// ---------------- log-sparse scores / stats ---------------------------------
__global__ __launch_bounds__(256) void e1_scores(
    const float* __restrict__ qk, float* __restrict__ scores)
{
    int lane = threadIdx.x & 31, wid = threadIdx.x >> 5;
    int gw = blockIdx.x * 8 + wid;
    int t = gw & (T_ - 1);
    int h = (gw >> 11) & 15;
    int b = gw >> 15;
    const float* qrow = qk + (size_t)(b * T_ + t) * 2048 + h * 64;
    float q0 = qrow[lane], q1 = qrow[lane + 32];
    #pragma unroll
    for (int e = 0; e < 8; e++) {
        int ts = (t + (1 << e)) & (T_ - 1);
        const float* kr = qk + (size_t)(b * T_ + ts) * 2048 + 1024 + h * 64;
        float s = q0 * kr[lane] + q1 * kr[lane + 32];
        #pragma unroll
        for (int o = 16; o; o >>= 1) s += __shfl_xor_sync(0xffffffffu, s, o);
        if (lane == 0)
            scores[((size_t)((b * 16 + h) * 8 + e)) * T_ + t] = s * 0.125f;
    }
}

__global__ void e2_stats(const float* __restrict__ scores, float2* __restrict__ stats)
{
    __shared__ float red[256];
    int idx = blockIdx.x;
    const float* s = scores + (size_t)idx * T_;
    int tid = threadIdx.x;
    float m = -1e30f;
    for (int i = tid; i < T_; i += 256) m = fmaxf(m, s[i]);
    red[tid] = m; __syncthreads();
    for (int o = 128; o > 0; o >>= 1) {
        if (tid < o) red[tid] = fmaxf(red[tid], red[tid + o]);
        __syncthreads();
    }
    float mt = red[0]; __syncthreads();
    float sm = 0.f;
    for (int i = tid; i < T_; i += 256) sm += expf(s[i] - mt);
    red[tid] = sm; __syncthreads();
    for (int o = 128; o > 0; o >>= 1) {
        if (tid < o) red[tid] += red[tid + o];
        __syncthreads();
    }
    if (tid == 0) stats[idx] = make_float2(mt, red[0]);
}

// ---------------- attention: writes fp16 h/m planes (padded) ----------------
__global__ __launch_bounds__(256) void attn_kernel(
    const float* __restrict__ qk, const float* __restrict__ vbuf,
    const float* __restrict__ scores, const float2* __restrict__ stats,
    __half* __restrict__ ah, __half* __restrict__ am)
{
    __shared__ float st[8][65];
    int lane = threadIdx.x & 31, wid = threadIdx.x >> 5;
    int tc = blockIdx.x & 255;
    int h  = (blockIdx.x >> 8) & 15;
    int b  = blockIdx.x >> 12;
    int t  = tc * 8 + wid;

    const float* qrow = qk + (size_t)(b * T_ + t) * 2048 + h * 64;
    float q0 = qrow[lane], q1 = qrow[lane + 32];

    float sw[16];
    #pragma unroll
    for (int w = 0; w < 16; w++) {
        int tt = t - 15 + w;
        float s = 0.f;
        if (tt >= 0) {
            const float* kr = qk + (size_t)(b * T_ + tt) * 2048 + 1024 + h * 64;
            s = q0 * kr[lane] + q1 * kr[lane + 32];
            #pragma unroll
            for (int o = 16; o; o >>= 1) s += __shfl_xor_sync(0xffffffffu, s, o);
            s *= 0.125f;
        }
        sw[w] = s;
    }
    float m = sw[0];
    #pragma unroll
    for (int w = 1; w < 16; w++) m = fmaxf(m, sw[w]);
    float den = 0.f;
    #pragma unroll
    for (int w = 0; w < 16; w++) den += expf(sw[w] - m);
    float inv = 1.f / den;

    float a0 = 0.f, a1 = 0.f;
    #pragma unroll
    for (int w = 0; w < 16; w++) {
        int tt = t - 15 + w;
        if (tt >= 0) {
            float al = expf(sw[w] - m) * inv;
            const float* vr = vbuf + (size_t)(b * T_ + tt) * 1024 + h * 64;
            a0 += al * vr[lane];
            a1 += al * vr[lane + 32];
        }
    }
    const float* sc = scores + ((size_t)((b * 16 + h) * 8)) * T_ + t;
    #pragma unroll
    for (int e = 0; e < 8; e++) {
        float2 stv = stats[(b * 16 + h) * 8 + e];
        float al = expf(sc[(size_t)e * T_] - stv.x) / stv.y;
        int ts = (t + (1 << e)) & (T_ - 1);
        const float* vr = vbuf + (size_t)(b * T_ + ts) * 1024 + h * 64;
        a0 += al * vr[lane];
        a1 += al * vr[lane + 32];
    }
    st[wid][lane]      = a0;
    st[wid][lane + 32] = a1;
    __syncthreads();
    for (int idx = threadIdx.x; idx < 512; idx += 256) {
        int d = idx >> 3, tt = idx & 7;
        float v = st[tt][d];
        __half hh = __float2half(v);
        __half mm = __float2half(v - __half2float(hh));
        size_t off = ((size_t)b * TPAD + 15 + tc * 8 + tt) * D_ + h * 64 + d;
        ah[off] = hh;
        am[off] = mm;
    }
}

// ---------------- launch ----------------------------------------------------
extern "C" void kernel_launch(void* const* d_in, const int* in_sizes, int n_in,
                              void* d_out, int out_size)
{
    const float* x   = (const float*)d_in[0];
    const float* q_w = (const float*)d_in[1];
    const float* q_b = (const float*)d_in[2];
    const float* k_w = (const float*)d_in[3];
    const float* k_b = (const float*)d_in[4];
    const float* v_w = (const float*)d_in[5];
    const float* v_b = (const float*)d_in[6];
    const float* p_w = (const float*)d_in[7];
    const float* p_b = (const float*)d_in[8];
    (void)in_sizes; (void)n_in; (void)out_size;

    void *xh, *xm, *wqkh, *wqkm, *wvh, *wvm, *wph, *wpm, *ah, *am;
    float *qk, *vbuf, *qkb, *scores;
    float2* stats;
    cudaGetSymbolAddress(&xh, g_xh_);     cudaGetSymbolAddress(&xm, g_xm_);
    cudaGetSymbolAddress(&wqkh, g_wqkh_); cudaGetSymbolAddress(&wqkm, g_wqkm_);
    cudaGetSymbolAddress(&wvh, g_wvh_);   cudaGetSymbolAddress(&wvm, g_wvm_);
    cudaGetSymbolAddress(&wph, g_wph_);   cudaGetSymbolAddress(&wpm, g_wpm_);
    cudaGetSymbolAddress(&ah, g_ah_);     cudaGetSymbolAddress(&am, g_am_);
    cudaGetSymbolAddress((void**)&qk, g_qk);
    cudaGetSymbolAddress((void**)&vbuf, g_v);
    cudaGetSymbolAddress((void**)&qkb, g_qkb);
    cudaGetSymbolAddress((void**)&scores, g_scores);
    cudaGetSymbolAddress((void**)&stats, g_stats);

    cudaFuncSetAttribute(gemm_hmma, cudaFuncAttributeMaxDynamicSharedMemorySize, SMEM_TOTAL);

    split_x<<<(int)((size_t)B_*TPAD*D_/256), 256>>>((__half*)xh, (__half*)xm, x);
    split_wqk<<<2*D_*D_/256, 256>>>((__half*)wqkh, (__half*)wqkm, q_w, k_w);
    split_w1<<<D_*D_/256, 256>>>((__half*)wvh, (__half*)wvm, v_w);
    split_w1<<<D_*D_/256, 256>>>((__half*)wph, (__half*)wpm, p_w);
    zero_apad<<<B_*16*D_/256, 256>>>((__half*)ah, (__half*)am);
    concat_bias<<<2*D_/256, 256>>>(qkb, q_b, k_b);

    // q+k causal conv: one HMMA GEMM over 16 w-phases (K = 16384)
    gemm_hmma<<<dim3(2*D_/NT, BT_/MT), 256, SMEM_TOTAL>>>(
        qk, (const __half*)xh, (const __half*)xm,
        (const __half*)wqkh, (const __half*)wqkm, qkb, 2*D_, 16, 0);
    // v projection
    gemm_hmma<<<dim3(D_/NT, BT_/MT), 256, SMEM_TOTAL>>>(
        vbuf, (const __half*)xh, (const __half*)xm,
        (const __half*)wvh, (const __half*)wvm, v_b, D_, 1, 15);
    // attention
    e1_scores<<<B_*H_*T_/8, 256>>>(qk, scores);
    e2_stats<<<B_*H_*E_, 256>>>(scores, stats);
    attn_kernel<<<B_*H_*T_/8, 256>>>(qk, vbuf, scores, stats, (__half*)ah, (__half*)am);
    // output projection -> d_out
    gemm_hmma<<<dim3(D_/NT, BT_/MT), 256, SMEM_TOTAL>>>(
        (float*)d_out, (const __half*)ah, (const __half*)am,
        (const __half*)wph, (const __half*)wpm, p_b, D_, 1, 15);
}

// round 9
// speedup vs baseline: 2.7415x; 1.2401x over previous
#include <cuda_runtime.h>
#include <cuda_fp16.h>
#include <math.h>
#include <stdint.h>

#define B_   2
#define T_   2048
#define D_   1024
#define H_   16
#define W_   16
#define E_   8
#define BT_  (B_*T_)
#define TPAD (T_+16)

#define MT 128
#define NT 256
// smem stage layout (bytes): A hi|A lo (128 rows x 80B) then B hi|B lo (256 x 80B)
#define A_PLANE 10240
#define B_PLANE 20480
#define STAGE_B 61440
#define NSTAGE  3
#define SMEM_TOTAL (NSTAGE*STAGE_B)   // 184320

// ---------------- device scratch -------------------------------------------
__device__ uint4 g_xh_  [B_*TPAD*D_/8];
__device__ uint4 g_xm_  [B_*TPAD*D_/8];
__device__ uint4 g_wqkh_[(size_t)W_*2*D_*D_/8];  // [w][n(q|k)][i] hi
__device__ uint4 g_wqkm_[(size_t)W_*2*D_*D_/8];
__device__ uint4 g_wvh_ [D_*D_/8];
__device__ uint4 g_wvm_ [D_*D_/8];
__device__ uint4 g_wph_ [D_*D_/8];
__device__ uint4 g_wpm_ [D_*D_/8];
__device__ uint4 g_ah_  [B_*TPAD*D_/8];
__device__ uint4 g_am_  [B_*TPAD*D_/8];
__device__ float g_qk   [BT_*2*D_];
__device__ float g_v    [BT_*D_];
__device__ float g_qkb  [2*D_];
__device__ float g_scores[B_*H_*E_*T_];
__device__ float2 g_stats[B_*H_*E_];

// ---------------- helpers ---------------------------------------------------
__device__ __forceinline__ uint32_t smem_u32(const void* p) {
    uint32_t a;
    asm("{ .reg .u64 t; cvta.to.shared.u64 t, %1; cvt.u32.u64 %0, t; }" : "=r"(a) : "l"(p));
    return a;
}
__device__ __forceinline__ void ldsm4(uint32_t* r, uint32_t a) {
    asm volatile("ldmatrix.sync.aligned.m8n8.x4.shared.b16 {%0,%1,%2,%3}, [%4];"
                 : "=r"(r[0]), "=r"(r[1]), "=r"(r[2]), "=r"(r[3]) : "r"(a));
}
__device__ __forceinline__ void mma16(float* c, const uint32_t* a, const uint32_t* b) {
    asm volatile("mma.sync.aligned.m16n8k16.row.col.f32.f16.f16.f32 "
        "{%0,%1,%2,%3},{%4,%5,%6,%7},{%8,%9},{%0,%1,%2,%3};\n"
        : "+f"(c[0]), "+f"(c[1]), "+f"(c[2]), "+f"(c[3])
        : "r"(a[0]), "r"(a[1]), "r"(a[2]), "r"(a[3]), "r"(b[0]), "r"(b[1]));
}
#define CP16(dst, src) asm volatile("cp.async.cg.shared.global [%0], [%1], 16;" \
    :: "r"(dst), "l"(src))

// ---------------- prep kernels ---------------------------------------------
__global__ __launch_bounds__(256) void split_x(
    __half* __restrict__ xh, __half* __restrict__ xm, const float* __restrict__ x)
{
    size_t idx = (size_t)blockIdx.x * 256 + threadIdx.x;
    int d = idx & (D_ - 1);
    int p = (idx >> 10) % TPAD;
    int b = (int)(idx / ((size_t)TPAD * D_));
    float v = 0.f;
    int t = p - 15;
    if (t >= 0 && t < T_) v = x[((size_t)b * T_ + t) * D_ + d];
    __half h = __float2half(v);
    xh[idx] = h;
    xm[idx] = __float2half(v - __half2float(h));
}

// coalesced weight repack: out[w][n][i] from q_w/k_w [o][i][w], via smem staging
// one warp handles (n, i0) with a 64-wide i chunk
__global__ __launch_bounds__(256) void split_wqk(
    __half* __restrict__ oh, __half* __restrict__ om,
    const float* __restrict__ qw, const float* __restrict__ kw)
{
    __shared__ float stg[8][64][17];
    int warp = threadIdx.x >> 5, lane = threadIdx.x & 31;
    int g = blockIdx.x * 8 + warp;               // 0 .. 2048*16-1
    int n = g >> 4, i0 = (g & 15) * 64;
    const float* src = (n < D_) ? (qw + ((size_t)n * D_ + i0) * W_)
                                : (kw + ((size_t)(n - D_) * D_ + i0) * W_);
    float (*S)[17] = stg[warp];
    const float4* s4 = (const float4*)src;       // 256 float4 (64 i x 16 w)
    #pragma unroll
    for (int j = 0; j < 8; j++) {
        float4 f = s4[lane + j * 32];
        int base = (lane + j * 32) * 4;
        S[(base    ) >> 4][(base    ) & 15] = f.x;
        S[(base + 1) >> 4][(base + 1) & 15] = f.y;
        S[(base + 2) >> 4][(base + 2) & 15] = f.z;
        S[(base + 3) >> 4][(base + 3) & 15] = f.w;
    }
    __syncwarp();
    #pragma unroll
    for (int w = 0; w < W_; w++) {
        float v0 = S[2 * lane][w], v1 = S[2 * lane + 1][w];
        __half h0 = __float2half(v0), h1 = __float2half(v1);
        __half m0 = __float2half(v0 - __half2float(h0));
        __half m1 = __float2half(v1 - __half2float(h1));
        size_t o = ((size_t)w * 2 * D_ + n) * D_ + i0 + 2 * lane;
        *(__half2*)(oh + o) = __halves2half2(h0, h1);
        *(__half2*)(om + o) = __halves2half2(m0, m1);
    }
}

__global__ __launch_bounds__(256) void split_w1(
    __half* __restrict__ oh, __half* __restrict__ om, const float* __restrict__ w)
{
    size_t idx = (size_t)blockIdx.x * 256 + threadIdx.x;
    float v = w[idx];
    __half h = __float2half(v);
    oh[idx] = h;
    om[idx] = __float2half(v - __half2float(h));
}

__global__ void zero_apad(__half* __restrict__ ah, __half* __restrict__ am) {
    int idx = blockIdx.x * 256 + threadIdx.x;
    int d = idx & (D_ - 1), p = (idx >> 10) % 16, b = idx / (16 * D_);
    int row = (p < 15) ? p : (TPAD - 1);
    size_t o = ((size_t)b * TPAD + row) * D_ + d;
    ah[o] = __float2half(0.f);
    am[o] = __float2half(0.f);
}

__global__ void concat_bias(float* __restrict__ d, const float* __restrict__ qb,
                            const float* __restrict__ kb) {
    int i = blockIdx.x * 256 + threadIdx.x;
    d[i] = (i < D_) ? qb[i] : kb[i - D_];
}

// ---------------- HMMA GEMM: 128x256 block, 512 threads, 3-stage ------------
// C[b*T+t][n] = sum_{w<wcount} sum_k A[b*TPAD + t0+m+wbase+w][k] * Bp[w][n][k] + bias[n]
__global__ __launch_bounds__(512, 1) void gemm_hmma(
    float* __restrict__ C,
    const __half* __restrict__ Ah, const __half* __restrict__ Am,
    const __half* __restrict__ Bh, const __half* __restrict__ Bm,
    const float* __restrict__ bias, int Ntot, int wcount, int wbase)
{
    extern __shared__ __align__(1024) char smem[];
    const uint32_t sb = smem_u32(smem);
    const int tid = threadIdx.x, warp = tid >> 5, lane = tid & 31;
    const int wm = warp >> 2, wn = warp & 3;       // 4x4 warp grid, tile 32x64
    const int m0 = blockIdx.y * MT, n0 = blockIdx.x * NT;
    const int b = m0 >> 11, t0 = m0 & (T_ - 1);
    const size_t arow0 = (size_t)b * TPAD + t0 + wbase;

    const int kt = D_ / 32;
    const int ns = wcount * kt;

    auto load_stage = [&](int s) {
        const int w = s / kt, k0 = (s % kt) * 32;
        const uint32_t st = sb + (s % NSTAGE) * STAGE_B;
        #pragma unroll
        for (int j = 0; j < 2; j++) {              // A: 1024 16B chunks
            int idx = tid + j * 512;
            int c = idx & 3, row = (idx >> 2) & 127, pl = idx >> 9;
            const __half* src = (pl ? Am : Ah) + (arow0 + w + row) * D_ + k0 + c * 8;
            CP16(st + pl * A_PLANE + row * 80 + c * 16, src);
        }
        #pragma unroll
        for (int j = 0; j < 4; j++) {              // B: 2048 16B chunks
            int idx = tid + j * 512;
            int c = idx & 3, row = (idx >> 2) & 255, pl = idx >> 10;
            const __half* src = (pl ? Bm : Bh)
                + ((size_t)w * Ntot + n0 + row) * (size_t)D_ + k0 + c * 8;
            CP16(st + 2 * A_PLANE + pl * B_PLANE + row * 80 + c * 16, src);
        }
        asm volatile("cp.async.commit_group;");
    };

    float acc[2][8][4];
    #pragma unroll
    for (int i = 0; i < 2; i++)
        #pragma unroll
        for (int j = 0; j < 8; j++)
            #pragma unroll
            for (int q = 0; q < 4; q++) acc[i][j][q] = 0.f;

    const int la = lane & 7, g1 = (lane >> 3) & 1, g2 = lane >> 4;
    const int arow_l = wm * 32 + g1 * 8 + la;
    const int brow_l = wn * 64 + g2 * 8 + la;

    load_stage(0);
    if (ns > 1) load_stage(1);
    for (int s = 0; s < ns; s++) {
        if (s + 1 < ns) { asm volatile("cp.async.wait_group 1;" ::: "memory"); }
        else            { asm volatile("cp.async.wait_group 0;" ::: "memory"); }
        __syncthreads();
        if (s + 2 < ns) load_stage(s + 2);

        const uint32_t st  = sb + (s % NSTAGE) * STAGE_B;
        const uint32_t Abh = st, Abm = st + A_PLANE;
        const uint32_t Bbh = st + 2 * A_PLANE, Bbm = Bbh + B_PLANE;
        #pragma unroll
        for (int kh = 0; kh < 2; kh++) {
            const int acol = kh * 32 + g2 * 16;
            const int bcol = kh * 32 + g1 * 16;
            uint32_t ah[2][4], am[2][4];
            #pragma unroll
            for (int mt = 0; mt < 2; mt++) {
                uint32_t off = (arow_l + mt * 16) * 80 + acol;
                ldsm4(ah[mt], Abh + off);
                ldsm4(am[mt], Abm + off);
            }
            #pragma unroll
            for (int ntp = 0; ntp < 4; ntp++) {
                uint32_t boff = (brow_l + ntp * 16) * 80 + bcol;
                uint32_t bh[4], bm[4];
                ldsm4(bh, Bbh + boff);
                ldsm4(bm, Bbm + boff);
                #pragma unroll
                for (int mt = 0; mt < 2; mt++) {
                    #pragma unroll
                    for (int hn = 0; hn < 2; hn++) {
                        float* a = acc[mt][ntp * 2 + hn];
                        mma16(a, ah[mt], bh + 2 * hn);
                        mma16(a, ah[mt], bm + 2 * hn);
                        mma16(a, am[mt], bh + 2 * hn);
                    }
                }
            }
        }
    }

    // epilogue
    const int er = lane >> 2, ec = (lane & 3) * 2;
    #pragma unroll
    for (int mt = 0; mt < 2; mt++) {
        int row = m0 + wm * 32 + mt * 16 + er;
        #pragma unroll
        for (int nt = 0; nt < 8; nt++) {
            int col = n0 + wn * 64 + nt * 8 + ec;
            float b0 = bias[col], b1 = bias[col + 1];
            float* a = acc[mt][nt];
            *(float2*)&C[(size_t)row * Ntot + col] = make_float2(a[0] + b0, a[1] + b1);
            *(float2*)&C[(size_t)(row + 8) * Ntot + col] = make_float2(a[2] + b0, a[3] + b1);
        }
    }
}

// ---------------- log-sparse scores / stats ---------------------------------
__global__ __launch_bounds__(256) void e1_scores(
    const float* __restrict__ qk, float* __restrict__ scores)
{
    int lane = threadIdx.x & 31, wid = threadIdx.x >> 5;
    int gw = blockIdx.x * 8 + wid;
    int t = gw & (T_ - 1);
    int h = (gw >> 11) & 15;
    int b = gw >> 15;
    const float* qrow = qk + (size_t)(b * T_ + t) * 2048 + h * 64;
    float q0 = qrow[lane], q1 = qrow[lane + 32];
    #pragma unroll
    for (int e = 0; e < 8; e++) {
        int ts = (t + (1 << e)) & (T_ - 1);
        const float* kr = qk + (size_t)(b * T_ + ts) * 2048 + 1024 + h * 64;
        float s = q0 * kr[lane] + q1 * kr[lane + 32];
        #pragma unroll
        for (int o = 16; o; o >>= 1) s += __shfl_xor_sync(0xffffffffu, s, o);
        if (lane == 0)
            scores[((size_t)((b * 16 + h) * 8 + e)) * T_ + t] = s * 0.125f;
    }
}

__global__ void e2_stats(const float* __restrict__ scores, float2* __restrict__ stats)
{
    __shared__ float red[256];
    int idx = blockIdx.x;
    const float* s = scores + (size_t)idx * T_;
    int tid = threadIdx.x;
    float m = -1e30f;
    for (int i = tid; i < T_; i += 256) m = fmaxf(m, s[i]);
    red[tid] = m; __syncthreads();
    for (int o = 128; o > 0; o >>= 1) {
        if (tid < o) red[tid] = fmaxf(red[tid], red[tid + o]);
        __syncthreads();
    }
    float mt = red[0]; __syncthreads();
    float sm = 0.f;
    for (int i = tid; i < T_; i += 256) sm += expf(s[i] - mt);
    red[tid] = sm; __syncthreads();
    for (int o = 128; o > 0; o >>= 1) {
        if (tid < o) red[tid] += red[tid + o];
        __syncthreads();
    }
    if (tid == 0) stats[idx] = make_float2(mt, red[0]);
}

// ---------------- attention: writes fp16 h/m planes (padded) ----------------
__global__ __launch_bounds__(256) void attn_kernel(
    const float* __restrict__ qk, const float* __restrict__ vbuf,
    const float* __restrict__ scores, const float2* __restrict__ stats,
    __half* __restrict__ ah, __half* __restrict__ am)
{
    __shared__ float st[8][65];
    int lane = threadIdx.x & 31, wid = threadIdx.x >> 5;
    int tc = blockIdx.x & 255;
    int h  = (blockIdx.x >> 8) & 15;
    int b  = blockIdx.x >> 12;
    int t  = tc * 8 + wid;

    const float* qrow = qk + (size_t)(b * T_ + t) * 2048 + h * 64;
    float q0 = qrow[lane], q1 = qrow[lane + 32];

    float sw[16];
    #pragma unroll
    for (int w = 0; w < 16; w++) {
        int tt = t - 15 + w;
        float s = 0.f;
        if (tt >= 0) {
            const float* kr = qk + (size_t)(b * T_ + tt) * 2048 + 1024 + h * 64;
            s = q0 * kr[lane] + q1 * kr[lane + 32];
            #pragma unroll
            for (int o = 16; o; o >>= 1) s += __shfl_xor_sync(0xffffffffu, s, o);
            s *= 0.125f;
        }
        sw[w] = s;
    }
    float m = sw[0];
    #pragma unroll
    for (int w = 1; w < 16; w++) m = fmaxf(m, sw[w]);
    float den = 0.f;
    #pragma unroll
    for (int w = 0; w < 16; w++) den += expf(sw[w] - m);
    float inv = 1.f / den;

    float a0 = 0.f, a1 = 0.f;
    #pragma unroll
    for (int w = 0; w < 16; w++) {
        int tt = t - 15 + w;
        if (tt >= 0) {
            float al = expf(sw[w] - m) * inv;
            const float* vr = vbuf + (size_t)(b * T_ + tt) * 1024 + h * 64;
            a0 += al * vr[lane];
            a1 += al * vr[lane + 32];
        }
    }
    const float* sc = scores + ((size_t)((b * 16 + h) * 8)) * T_ + t;
    #pragma unroll
    for (int e = 0; e < 8; e++) {
        float2 stv = stats[(b * 16 + h) * 8 + e];
        float al = expf(sc[(size_t)e * T_] - stv.x) / stv.y;
        int ts = (t + (1 << e)) & (T_ - 1);
        const float* vr = vbuf + (size_t)(b * T_ + ts) * 1024 + h * 64;
        a0 += al * vr[lane];
        a1 += al * vr[lane + 32];
    }
    st[wid][lane]      = a0;
    st[wid][lane + 32] = a1;
    __syncthreads();
    for (int idx = threadIdx.x; idx < 512; idx += 256) {
        int d = idx >> 3, tt = idx & 7;
        float v = st[tt][d];
        __half hh = __float2half(v);
        __half mm = __float2half(v - __half2float(hh));
        size_t off = ((size_t)b * TPAD + 15 + tc * 8 + tt) * D_ + h * 64 + d;
        ah[off] = hh;
        am[off] = mm;
    }
}

// ---------------- launch ----------------------------------------------------
extern "C" void kernel_launch(void* const* d_in, const int* in_sizes, int n_in,
                              void* d_out, int out_size)
{
    const float* x   = (const float*)d_in[0];
    const float* q_w = (const float*)d_in[1];
    const float* q_b = (const float*)d_in[2];
    const float* k_w = (const float*)d_in[3];
    const float* k_b = (const float*)d_in[4];
    const float* v_w = (const float*)d_in[5];
    const float* v_b = (const float*)d_in[6];
    const float* p_w = (const float*)d_in[7];
    const float* p_b = (const float*)d_in[8];
    (void)in_sizes; (void)n_in; (void)out_size;

    void *xh, *xm, *wqkh, *wqkm, *wvh, *wvm, *wph, *wpm, *ah, *am;
    float *qk, *vbuf, *qkb, *scores;
    float2* stats;
    cudaGetSymbolAddress(&xh, g_xh_);     cudaGetSymbolAddress(&xm, g_xm_);
    cudaGetSymbolAddress(&wqkh, g_wqkh_); cudaGetSymbolAddress(&wqkm, g_wqkm_);
    cudaGetSymbolAddress(&wvh, g_wvh_);   cudaGetSymbolAddress(&wvm, g_wvm_);
    cudaGetSymbolAddress(&wph, g_wph_);   cudaGetSymbolAddress(&wpm, g_wpm_);
    cudaGetSymbolAddress(&ah, g_ah_);     cudaGetSymbolAddress(&am, g_am_);
    cudaGetSymbolAddress((void**)&qk, g_qk);
    cudaGetSymbolAddress((void**)&vbuf, g_v);
    cudaGetSymbolAddress((void**)&qkb, g_qkb);
    cudaGetSymbolAddress((void**)&scores, g_scores);
    cudaGetSymbolAddress((void**)&stats, g_stats);

    cudaFuncSetAttribute(gemm_hmma, cudaFuncAttributeMaxDynamicSharedMemorySize, SMEM_TOTAL);

    split_x<<<(int)((size_t)B_*TPAD*D_/256), 256>>>((__half*)xh, (__half*)xm, x);
    split_wqk<<<2*D_*16/8, 256>>>((__half*)wqkh, (__half*)wqkm, q_w, k_w);
    split_w1<<<D_*D_/256, 256>>>((__half*)wvh, (__half*)wvm, v_w);
    split_w1<<<D_*D_/256, 256>>>((__half*)wph, (__half*)wpm, p_w);
    zero_apad<<<B_*16*D_/256, 256>>>((__half*)ah, (__half*)am);
    concat_bias<<<2*D_/256, 256>>>(qkb, q_b, k_b);

    // q+k causal conv: one HMMA GEMM over 16 w-phases (K = 16384)
    gemm_hmma<<<dim3(2*D_/NT, BT_/MT), 512, SMEM_TOTAL>>>(
        qk, (const __half*)xh, (const __half*)xm,
        (const __half*)wqkh, (const __half*)wqkm, qkb, 2*D_, 16, 0);
    // v projection
    gemm_hmma<<<dim3(D_/NT, BT_/MT), 512, SMEM_TOTAL>>>(
        vbuf, (const __half*)xh, (const __half*)xm,
        (const __half*)wvh, (const __half*)wvm, v_b, D_, 1, 15);
    // attention
    e1_scores<<<B_*H_*T_/8, 256>>>(qk, scores);
    e2_stats<<<B_*H_*E_, 256>>>(scores, stats);
    attn_kernel<<<B_*H_*T_/8, 256>>>(qk, vbuf, scores, stats, (__half*)ah, (__half*)am);
    // output projection -> d_out
    gemm_hmma<<<dim3(D_/NT, BT_/MT), 512, SMEM_TOTAL>>>(
        (float*)d_out, (const __half*)ah, (const __half*)am,
        (const __half*)wph, (const __half*)wpm, p_b, D_, 1, 15);
}

// round 11
// speedup vs baseline: 2.7437x; 1.0008x over previous
#include <cuda_runtime.h>
#include <cuda_fp16.h>
#include <math.h>
#include <stdint.h>

#define B_   2
#define T_   2048
#define D_   1024
#define H_   16
#define W_   16
#define E_   8
#define BT_  (B_*T_)
#define TPAD (T_+16)

#define MT 128
#define NT 256
#define A_PLANE 10240
#define B_PLANE 20480
#define STAGE_B 61440
#define NSTAGE  3
#define SMEM_TOTAL (NSTAGE*STAGE_B)   // 184320

// ---------------- device scratch -------------------------------------------
__device__ uint4 g_xh_  [B_*TPAD*D_/8];
__device__ uint4 g_xm_  [B_*TPAD*D_/8];
__device__ uint4 g_wqkh_[(size_t)W_*2*D_*D_/8];  // [w][n(q|k)][i] hi
__device__ uint4 g_wqkm_[(size_t)W_*2*D_*D_/8];
__device__ uint4 g_wvh_ [D_*D_/8];
__device__ uint4 g_wvm_ [D_*D_/8];
__device__ uint4 g_wph_ [D_*D_/8];
__device__ uint4 g_wpm_ [D_*D_/8];
__device__ uint4 g_ah_  [B_*TPAD*D_/8];
__device__ uint4 g_am_  [B_*TPAD*D_/8];
__device__ float g_qk   [BT_*2*D_];
__device__ float g_v    [BT_*D_];
__device__ float g_qkb  [2*D_];
__device__ float g_scores[B_*H_*E_*T_];
__device__ float2 g_stats[B_*H_*E_];

// ---------------- helpers ---------------------------------------------------
__device__ __forceinline__ uint32_t smem_u32(const void* p) {
    uint32_t a;
    asm("{ .reg .u64 t; cvta.to.shared.u64 t, %1; cvt.u32.u64 %0, t; }" : "=r"(a) : "l"(p));
    return a;
}
__device__ __forceinline__ void ldsm4(uint32_t* r, uint32_t a) {
    asm volatile("ldmatrix.sync.aligned.m8n8.x4.shared.b16 {%0,%1,%2,%3}, [%4];"
                 : "=r"(r[0]), "=r"(r[1]), "=r"(r[2]), "=r"(r[3]) : "r"(a));
}
__device__ __forceinline__ void mma16(float* c, const uint32_t* a, const uint32_t* b) {
    asm volatile("mma.sync.aligned.m16n8k16.row.col.f32.f16.f16.f32 "
        "{%0,%1,%2,%3},{%4,%5,%6,%7},{%8,%9},{%0,%1,%2,%3};\n"
        : "+f"(c[0]), "+f"(c[1]), "+f"(c[2]), "+f"(c[3])
        : "r"(a[0]), "r"(a[1]), "r"(a[2]), "r"(a[3]), "r"(b[0]), "r"(b[1]));
}
#define CP16(dst, src) asm volatile("cp.async.cg.shared.global [%0], [%1], 16;" \
    :: "r"(dst), "l"(src))

// ---------------- prep kernels ---------------------------------------------
__global__ __launch_bounds__(256) void split_x(
    __half* __restrict__ xh, __half* __restrict__ xm, const float* __restrict__ x)
{
    size_t idx = (size_t)blockIdx.x * 256 + threadIdx.x;
    int d = idx & (D_ - 1);
    int p = (idx >> 10) % TPAD;
    int b = (int)(idx / ((size_t)TPAD * D_));
    float v = 0.f;
    int t = p - 15;
    if (t >= 0 && t < T_) v = x[((size_t)b * T_ + t) * D_ + d];
    __half h = __float2half(v);
    xh[idx] = h;
    xm[idx] = __float2half(v - __half2float(h));
}

// coalesced weight repack: out[w][n][i] from q_w/k_w [o][i][w], via smem staging
__global__ __launch_bounds__(256) void split_wqk(
    __half* __restrict__ oh, __half* __restrict__ om,
    const float* __restrict__ qw, const float* __restrict__ kw)
{
    __shared__ float stg[8][64][17];
    int warp = threadIdx.x >> 5, lane = threadIdx.x & 31;
    int g = blockIdx.x * 8 + warp;
    int n = g >> 4, i0 = (g & 15) * 64;
    const float* src = (n < D_) ? (qw + ((size_t)n * D_ + i0) * W_)
                                : (kw + ((size_t)(n - D_) * D_ + i0) * W_);
    float (*S)[17] = stg[warp];
    const float4* s4 = (const float4*)src;
    #pragma unroll
    for (int j = 0; j < 8; j++) {
        float4 f = s4[lane + j * 32];
        int base = (lane + j * 32) * 4;
        S[(base    ) >> 4][(base    ) & 15] = f.x;
        S[(base + 1) >> 4][(base + 1) & 15] = f.y;
        S[(base + 2) >> 4][(base + 2) & 15] = f.z;
        S[(base + 3) >> 4][(base + 3) & 15] = f.w;
    }
    __syncwarp();
    #pragma unroll
    for (int w = 0; w < W_; w++) {
        float v0 = S[2 * lane][w], v1 = S[2 * lane + 1][w];
        __half h0 = __float2half(v0), h1 = __float2half(v1);
        __half m0 = __float2half(v0 - __half2float(h0));
        __half m1 = __float2half(v1 - __half2float(h1));
        size_t o = ((size_t)w * 2 * D_ + n) * D_ + i0 + 2 * lane;
        *(__half2*)(oh + o) = __halves2half2(h0, h1);
        *(__half2*)(om + o) = __halves2half2(m0, m1);
    }
}

__global__ __launch_bounds__(256) void split_w1(
    __half* __restrict__ oh, __half* __restrict__ om, const float* __restrict__ w)
{
    size_t idx = (size_t)blockIdx.x * 256 + threadIdx.x;
    float v = w[idx];
    __half h = __float2half(v);
    oh[idx] = h;
    om[idx] = __float2half(v - __half2float(h));
}

// merged: zero attn-plane pad rows + concat q/k bias (one launch)
__global__ void zero_concat(__half* __restrict__ ah, __half* __restrict__ am,
                            float* __restrict__ qkb,
                            const float* __restrict__ qb, const float* __restrict__ kb)
{
    int idx = blockIdx.x * 256 + threadIdx.x;
    if (idx < B_ * 16 * D_) {
        int d = idx & (D_ - 1), p = (idx >> 10) % 16, b = idx / (16 * D_);
        int row = (p < 15) ? p : (TPAD - 1);
        size_t o = ((size_t)b * TPAD + row) * D_ + d;
        ah[o] = __float2half(0.f);
        am[o] = __float2half(0.f);
    } else {
        int i = idx - B_ * 16 * D_;
        if (i < 2 * D_) qkb[i] = (i < D_) ? qb[i] : kb[i - D_];
    }
}

// ---------------- HMMA GEMM body: 128x256 tile, 512 threads, 3-stage --------
__device__ __forceinline__ void gemm_body(
    float* __restrict__ C,
    const __half* __restrict__ Ah, const __half* __restrict__ Am,
    const __half* __restrict__ Bh, const __half* __restrict__ Bm,
    const float* __restrict__ bias, int Ntot, int wcount, int wbase,
    int m0, int n0)
{
    extern __shared__ __align__(1024) char smem[];
    const uint32_t sb = smem_u32(smem);
    const int tid = threadIdx.x, warp = tid >> 5, lane = tid & 31;
    const int wm = warp >> 2, wn = warp & 3;
    const int b = m0 >> 11, t0 = m0 & (T_ - 1);
    const size_t arow0 = (size_t)b * TPAD + t0 + wbase;

    const int kt = D_ / 32;
    const int ns = wcount * kt;

    auto load_stage = [&](int s) {
        const int w = s / kt, k0 = (s % kt) * 32;
        const uint32_t st = sb + (s % NSTAGE) * STAGE_B;
        #pragma unroll
        for (int j = 0; j < 2; j++) {
            int idx = tid + j * 512;
            int c = idx & 3, row = (idx >> 2) & 127, pl = idx >> 9;
            const __half* src = (pl ? Am : Ah) + (arow0 + w + row) * D_ + k0 + c * 8;
            CP16(st + pl * A_PLANE + row * 80 + c * 16, src);
        }
        #pragma unroll
        for (int j = 0; j < 4; j++) {
            int idx = tid + j * 512;
            int c = idx & 3, row = (idx >> 2) & 255, pl = idx >> 10;
            const __half* src = (pl ? Bm : Bh)
                + ((size_t)w * Ntot + n0 + row) * (size_t)D_ + k0 + c * 8;
            CP16(st + 2 * A_PLANE + pl * B_PLANE + row * 80 + c * 16, src);
        }
        asm volatile("cp.async.commit_group;");
    };

    float acc[2][8][4];
    #pragma unroll
    for (int i = 0; i < 2; i++)
        #pragma unroll
        for (int j = 0; j < 8; j++)
            #pragma unroll
            for (int q = 0; q < 4; q++) acc[i][j][q] = 0.f;

    const int la = lane & 7, g1 = (lane >> 3) & 1, g2 = lane >> 4;
    const int arow_l = wm * 32 + g1 * 8 + la;
    const int brow_l = wn * 64 + g2 * 8 + la;

    load_stage(0);
    if (ns > 1) load_stage(1);
    for (int s = 0; s < ns; s++) {
        if (s + 1 < ns) { asm volatile("cp.async.wait_group 1;" ::: "memory"); }
        else            { asm volatile("cp.async.wait_group 0;" ::: "memory"); }
        __syncthreads();
        if (s + 2 < ns) load_stage(s + 2);

        const uint32_t st  = sb + (s % NSTAGE) * STAGE_B;
        const uint32_t Abh = st, Abm = st + A_PLANE;
        const uint32_t Bbh = st + 2 * A_PLANE, Bbm = Bbh + B_PLANE;
        #pragma unroll
        for (int kh = 0; kh < 2; kh++) {
            const int acol = kh * 32 + g2 * 16;
            const int bcol = kh * 32 + g1 * 16;
            uint32_t ah[2][4], am[2][4];
            #pragma unroll
            for (int mt = 0; mt < 2; mt++) {
                uint32_t off = (arow_l + mt * 16) * 80 + acol;
                ldsm4(ah[mt], Abh + off);
                ldsm4(am[mt], Abm + off);
            }
            #pragma unroll
            for (int ntp = 0; ntp < 4; ntp++) {
                uint32_t boff = (brow_l + ntp * 16) * 80 + bcol;
                uint32_t bh[4], bm[4];
                ldsm4(bh, Bbh + boff);
                ldsm4(bm, Bbm + boff);
                #pragma unroll
                for (int mt = 0; mt < 2; mt++) {
                    #pragma unroll
                    for (int hn = 0; hn < 2; hn++) {
                        float* a = acc[mt][ntp * 2 + hn];
                        mma16(a, ah[mt], bh + 2 * hn);
                        mma16(a, ah[mt], bm + 2 * hn);
                        mma16(a, am[mt], bh + 2 * hn);
                    }
                }
            }
        }
    }

    const int er = lane >> 2, ec = (lane & 3) * 2;
    #pragma unroll
    for (int mt = 0; mt < 2; mt++) {
        int row = m0 + wm * 32 + mt * 16 + er;
        #pragma unroll
        for (int nt = 0; nt < 8; nt++) {
            int col = n0 + wn * 64 + nt * 8 + ec;
            float b0 = bias[col], b1 = bias[col + 1];
            float* a = acc[mt][nt];
            *(float2*)&C[(size_t)row * Ntot + col] = make_float2(a[0] + b0, a[1] + b1);
            *(float2*)&C[(size_t)(row + 8) * Ntot + col] = make_float2(a[2] + b0, a[3] + b1);
        }
    }
}

// fused conv(q|k) + v-projection: tiles 0..255 conv, 256..383 v (tail backfill)
__global__ __launch_bounds__(512, 1) void gemm_fused(
    float* __restrict__ qk, float* __restrict__ vout,
    const __half* __restrict__ Ah, const __half* __restrict__ Am,
    const __half* __restrict__ Bqh, const __half* __restrict__ Bqm,
    const __half* __restrict__ Bvh, const __half* __restrict__ Bvm,
    const float* __restrict__ qkb, const float* __restrict__ vb)
{
    int id = blockIdx.x;
    float* C; const __half *Bh, *Bm; const float* bias;
    int Ntot, wcount, wbase, m0, n0;
    if (id < 256) {
        C = qk; Bh = Bqh; Bm = Bqm; bias = qkb;
        Ntot = 2 * D_; wcount = 16; wbase = 0;
        m0 = (id >> 3) * MT; n0 = (id & 7) * NT;
    } else {
        int j = id - 256;
        C = vout; Bh = Bvh; Bm = Bvm; bias = vb;
        Ntot = D_; wcount = 1; wbase = 15;
        m0 = (j >> 2) * MT; n0 = (j & 3) * NT;
    }
    gemm_body(C, Ah, Am, Bh, Bm, bias, Ntot, wcount, wbase, m0, n0);
}

// plain GEMM (p projection)
__global__ __launch_bounds__(512, 1) void gemm_hmma(
    float* __restrict__ C,
    const __half* __restrict__ Ah, const __half* __restrict__ Am,
    const __half* __restrict__ Bh, const __half* __restrict__ Bm,
    const float* __restrict__ bias, int Ntot, int wcount, int wbase)
{
    gemm_body(C, Ah, Am, Bh, Bm, bias, Ntot, wcount, wbase,
              blockIdx.y * MT, blockIdx.x * NT);
}

// ---------------- log-sparse scores / stats ---------------------------------
__global__ __launch_bounds__(256) void e1_scores(
    const float* __restrict__ qk, float* __restrict__ scores)
{
    int lane = threadIdx.x & 31, wid = threadIdx.x >> 5;
    int gw = blockIdx.x * 8 + wid;
    int t = gw & (T_ - 1);
    int h = (gw >> 11) & 15;
    int b = gw >> 15;
    const float* qrow = qk + (size_t)(b * T_ + t) * 2048 + h * 64;
    float q0 = qrow[lane], q1 = qrow[lane + 32];
    #pragma unroll
    for (int e = 0; e < 8; e++) {
        int ts = (t + (1 << e)) & (T_ - 1);
        const float* kr = qk + (size_t)(b * T_ + ts) * 2048 + 1024 + h * 64;
        float s = q0 * kr[lane] + q1 * kr[lane + 32];
        #pragma unroll
        for (int o = 16; o; o >>= 1) s += __shfl_xor_sync(0xffffffffu, s, o);
        if (lane == 0)
            scores[((size_t)((b * 16 + h) * 8 + e)) * T_ + t] = s * 0.125f;
    }
}

__global__ void e2_stats(const float* __restrict__ scores, float2* __restrict__ stats)
{
    __shared__ float red[256];
    int idx = blockIdx.x;
    const float* s = scores + (size_t)idx * T_;
    int tid = threadIdx.x;
    float m = -1e30f;
    for (int i = tid; i < T_; i += 256) m = fmaxf(m, s[i]);
    red[tid] = m; __syncthreads();
    for (int o = 128; o > 0; o >>= 1) {
        if (tid < o) red[tid] = fmaxf(red[tid], red[tid + o]);
        __syncthreads();
    }
    float mt = red[0]; __syncthreads();
    float sm = 0.f;
    for (int i = tid; i < T_; i += 256) sm += expf(s[i] - mt);
    red[tid] = sm; __syncthreads();
    for (int o = 128; o > 0; o >>= 1) {
        if (tid < o) red[tid] += red[tid + o];
        __syncthreads();
    }
    if (tid == 0) stats[idx] = make_float2(mt, red[0]);
}

// ---------------- attention: writes fp16 h/m planes (padded) ----------------
__global__ __launch_bounds__(256) void attn_kernel(
    const float* __restrict__ qk, const float* __restrict__ vbuf,
    const float* __restrict__ scores, const float2* __restrict__ stats,
    __half* __restrict__ ah, __half* __restrict__ am)
{
    __shared__ float st[8][65];
    int lane = threadIdx.x & 31, wid = threadIdx.x >> 5;
    int tc = blockIdx.x & 255;
    int h  = (blockIdx.x >> 8) & 15;
    int b  = blockIdx.x >> 12;
    int t  = tc * 8 + wid;

    const float* qrow = qk + (size_t)(b * T_ + t) * 2048 + h * 64;
    float q0 = qrow[lane], q1 = qrow[lane + 32];

    float sw[16];
    #pragma unroll
    for (int w = 0; w < 16; w++) {
        int tt = t - 15 + w;
        float s = 0.f;
        if (tt >= 0) {
            const float* kr = qk + (size_t)(b * T_ + tt) * 2048 + 1024 + h * 64;
            s = q0 * kr[lane] + q1 * kr[lane + 32];
            #pragma unroll
            for (int o = 16; o; o >>= 1) s += __shfl_xor_sync(0xffffffffu, s, o);
            s *= 0.125f;
        }
        sw[w] = s;
    }
    float m = sw[0];
    #pragma unroll
    for (int w = 1; w < 16; w++) m = fmaxf(m, sw[w]);
    float den = 0.f;
    #pragma unroll
    for (int w = 0; w < 16; w++) den += expf(sw[w] - m);
    float inv = 1.f / den;

    float a0 = 0.f, a1 = 0.f;
    #pragma unroll
    for (int w = 0; w < 16; w++) {
        int tt = t - 15 + w;
        if (tt >= 0) {
            float al = expf(sw[w] - m) * inv;
            const float* vr = vbuf + (size_t)(b * T_ + tt) * 1024 + h * 64;
            a0 += al * vr[lane];
            a1 += al * vr[lane + 32];
        }
    }
    const float* sc = scores + ((size_t)((b * 16 + h) * 8)) * T_ + t;
    #pragma unroll
    for (int e = 0; e < 8; e++) {
        float2 stv = stats[(b * 16 + h) * 8 + e];
        float al = expf(sc[(size_t)e * T_] - stv.x) / stv.y;
        int ts = (t + (1 << e)) & (T_ - 1);
        const float* vr = vbuf + (size_t)(b * T_ + ts) * 1024 + h * 64;
        a0 += al * vr[lane];
        a1 += al * vr[lane + 32];
    }
    st[wid][lane]      = a0;
    st[wid][lane + 32] = a1;
    __syncthreads();
    for (int idx = threadIdx.x; idx < 512; idx += 256) {
        int d = idx >> 3, tt = idx & 7;
        float v = st[tt][d];
        __half hh = __float2half(v);
        __half mm = __float2half(v - __half2float(hh));
        size_t off = ((size_t)b * TPAD + 15 + tc * 8 + tt) * D_ + h * 64 + d;
        ah[off] = hh;
        am[off] = mm;
    }
}

// ---------------- launch ----------------------------------------------------
extern "C" void kernel_launch(void* const* d_in, const int* in_sizes, int n_in,
                              void* d_out, int out_size)
{
    const float* x   = (const float*)d_in[0];
    const float* q_w = (const float*)d_in[1];
    const float* q_b = (const float*)d_in[2];
    const float* k_w = (const float*)d_in[3];
    const float* k_b = (const float*)d_in[4];
    const float* v_w = (const float*)d_in[5];
    const float* v_b = (const float*)d_in[6];
    const float* p_w = (const float*)d_in[7];
    const float* p_b = (const float*)d_in[8];
    (void)in_sizes; (void)n_in; (void)out_size;

    void *xh, *xm, *wqkh, *wqkm, *wvh, *wvm, *wph, *wpm, *ah, *am;
    float *qk, *vbuf, *qkb, *scores;
    float2* stats;
    cudaGetSymbolAddress(&xh, g_xh_);     cudaGetSymbolAddress(&xm, g_xm_);
    cudaGetSymbolAddress(&wqkh, g_wqkh_); cudaGetSymbolAddress(&wqkm, g_wqkm_);
    cudaGetSymbolAddress(&wvh, g_wvh_);   cudaGetSymbolAddress(&wvm, g_wvm_);
    cudaGetSymbolAddress(&wph, g_wph_);   cudaGetSymbolAddress(&wpm, g_wpm_);
    cudaGetSymbolAddress(&ah, g_ah_);     cudaGetSymbolAddress(&am, g_am_);
    cudaGetSymbolAddress((void**)&qk, g_qk);
    cudaGetSymbolAddress((void**)&vbuf, g_v);
    cudaGetSymbolAddress((void**)&qkb, g_qkb);
    cudaGetSymbolAddress((void**)&scores, g_scores);
    cudaGetSymbolAddress((void**)&stats, g_stats);

    cudaFuncSetAttribute(gemm_fused, cudaFuncAttributeMaxDynamicSharedMemorySize, SMEM_TOTAL);
    cudaFuncSetAttribute(gemm_hmma,  cudaFuncAttributeMaxDynamicSharedMemorySize, SMEM_TOTAL);

    // 5 prep launches, so the fused GEMM is launch #6 (ncu -s 5 -c 1 capture)
    split_x<<<(int)((size_t)B_*TPAD*D_/256), 256>>>((__half*)xh, (__half*)xm, x);
    split_wqk<<<2*D_*16/8, 256>>>((__half*)wqkh, (__half*)wqkm, q_w, k_w);
    split_w1<<<D_*D_/256, 256>>>((__half*)wvh, (__half*)wvm, v_w);
    split_w1<<<D_*D_/256, 256>>>((__half*)wph, (__half*)wpm, p_w);
    zero_concat<<<(B_*16*D_ + 2*D_ + 255)/256, 256>>>(
        (__half*)ah, (__half*)am, qkb, q_b, k_b);

    // fused q+k causal conv (256 tiles) + v projection (128 tiles, backfill)
    gemm_fused<<<384, 512, SMEM_TOTAL>>>(
        qk, vbuf, (const __half*)xh, (const __half*)xm,
        (const __half*)wqkh, (const __half*)wqkm,
        (const __half*)wvh, (const __half*)wvm, qkb, v_b);

    // attention
    e1_scores<<<B_*H_*T_/8, 256>>>(qk, scores);
    e2_stats<<<B_*H_*E_, 256>>>(scores, stats);
    attn_kernel<<<B_*H_*T_/8, 256>>>(qk, vbuf, scores, stats, (__half*)ah, (__half*)am);

    // output projection -> d_out
    gemm_hmma<<<dim3(D_/NT, BT_/MT), 512, SMEM_TOTAL>>>(
        (float*)d_out, (const __half*)ah, (const __half*)am,
        (const __half*)wph, (const __half*)wpm, p_b, D_, 1, 15);
}

// round 12
// speedup vs baseline: 2.8411x; 1.0355x over previous
#include <cuda_runtime.h>
#include <cuda_fp16.h>
#include <math.h>
#include <stdint.h>

#define B_   2
#define T_   2048
#define D_   1024
#define H_   16
#define W_   16
#define E_   8
#define BT_  (B_*T_)
#define TPAD (T_+16)

#define MT 128
#define NT 256
#define A_PLANE 10240
#define B_PLANE 20480
#define STAGE_B 61440
#define NSTAGE  3
#define SMEM_TOTAL (NSTAGE*STAGE_B)   // 184320

// stream-K stage space: conv tiles 0..255 (512 stages each), v tiles 256..383 (32 each)
#define CONV_STAGES 131072
#define G_STAGES    135168

// ---------------- device scratch -------------------------------------------
__device__ uint4 g_xh_  [B_*TPAD*D_/8];
__device__ uint4 g_xm_  [B_*TPAD*D_/8];
__device__ uint4 g_wqkh_[(size_t)W_*2*D_*D_/8];  // [w][n(q|k)][i] hi
__device__ uint4 g_wqkm_[(size_t)W_*2*D_*D_/8];
__device__ uint4 g_wvh_ [D_*D_/8];
__device__ uint4 g_wvm_ [D_*D_/8];
__device__ uint4 g_wph_ [D_*D_/8];
__device__ uint4 g_wpm_ [D_*D_/8];
__device__ uint4 g_ah_  [B_*TPAD*D_/8];
__device__ uint4 g_am_  [B_*TPAD*D_/8];
__device__ float g_qk   [BT_*2*D_];
__device__ float g_v    [BT_*D_];
__device__ float g_scores[B_*H_*E_*T_];
__device__ float2 g_stats[B_*H_*E_];

// ---------------- helpers ---------------------------------------------------
__device__ __forceinline__ uint32_t smem_u32(const void* p) {
    uint32_t a;
    asm("{ .reg .u64 t; cvta.to.shared.u64 t, %1; cvt.u32.u64 %0, t; }" : "=r"(a) : "l"(p));
    return a;
}
__device__ __forceinline__ void ldsm4(uint32_t* r, uint32_t a) {
    asm volatile("ldmatrix.sync.aligned.m8n8.x4.shared.b16 {%0,%1,%2,%3}, [%4];"
                 : "=r"(r[0]), "=r"(r[1]), "=r"(r[2]), "=r"(r[3]) : "r"(a));
}
__device__ __forceinline__ void mma16(float* c, const uint32_t* a, const uint32_t* b) {
    asm volatile("mma.sync.aligned.m16n8k16.row.col.f32.f16.f16.f32 "
        "{%0,%1,%2,%3},{%4,%5,%6,%7},{%8,%9},{%0,%1,%2,%3};\n"
        : "+f"(c[0]), "+f"(c[1]), "+f"(c[2]), "+f"(c[3])
        : "r"(a[0]), "r"(a[1]), "r"(a[2]), "r"(a[3]), "r"(b[0]), "r"(b[1]));
}
#define CP16(dst, src) asm volatile("cp.async.cg.shared.global [%0], [%1], 16;" \
    :: "r"(dst), "l"(src))

// ---------------- prep kernels ---------------------------------------------
__global__ __launch_bounds__(256) void split_x(
    __half* __restrict__ xh, __half* __restrict__ xm, const float* __restrict__ x)
{
    size_t idx = (size_t)blockIdx.x * 256 + threadIdx.x;
    int d = idx & (D_ - 1);
    int p = (idx >> 10) % TPAD;
    int b = (int)(idx / ((size_t)TPAD * D_));
    float v = 0.f;
    int t = p - 15;
    if (t >= 0 && t < T_) v = x[((size_t)b * T_ + t) * D_ + d];
    __half h = __float2half(v);
    xh[idx] = h;
    xm[idx] = __float2half(v - __half2float(h));
}

// coalesced weight repack: out[w][n][i] from q_w/k_w [o][i][w], via smem staging
__global__ __launch_bounds__(256) void split_wqk(
    __half* __restrict__ oh, __half* __restrict__ om,
    const float* __restrict__ qw, const float* __restrict__ kw)
{
    __shared__ float stg[8][64][17];
    int warp = threadIdx.x >> 5, lane = threadIdx.x & 31;
    int g = blockIdx.x * 8 + warp;
    int n = g >> 4, i0 = (g & 15) * 64;
    const float* src = (n < D_) ? (qw + ((size_t)n * D_ + i0) * W_)
                                : (kw + ((size_t)(n - D_) * D_ + i0) * W_);
    float (*S)[17] = stg[warp];
    const float4* s4 = (const float4*)src;
    #pragma unroll
    for (int j = 0; j < 8; j++) {
        float4 f = s4[lane + j * 32];
        int base = (lane + j * 32) * 4;
        S[(base    ) >> 4][(base    ) & 15] = f.x;
        S[(base + 1) >> 4][(base + 1) & 15] = f.y;
        S[(base + 2) >> 4][(base + 2) & 15] = f.z;
        S[(base + 3) >> 4][(base + 3) & 15] = f.w;
    }
    __syncwarp();
    #pragma unroll
    for (int w = 0; w < W_; w++) {
        float v0 = S[2 * lane][w], v1 = S[2 * lane + 1][w];
        __half h0 = __float2half(v0), h1 = __float2half(v1);
        __half m0 = __float2half(v0 - __half2float(h0));
        __half m1 = __float2half(v1 - __half2float(h1));
        size_t o = ((size_t)w * 2 * D_ + n) * D_ + i0 + 2 * lane;
        *(__half2*)(oh + o) = __halves2half2(h0, h1);
        *(__half2*)(om + o) = __halves2half2(m0, m1);
    }
}

__global__ __launch_bounds__(256) void split_w1(
    __half* __restrict__ oh, __half* __restrict__ om, const float* __restrict__ w)
{
    size_t idx = (size_t)blockIdx.x * 256 + threadIdx.x;
    float v = w[idx];
    __half h = __float2half(v);
    oh[idx] = h;
    om[idx] = __float2half(v - __half2float(h));
}

// prefill: qk <- bias(q|k), v <- bias(v), attn planes pad rows <- 0
// f4-unit index space: [0, 2097152) qk | [.., +1048576) v | [.., +8192) pads
__global__ __launch_bounds__(256) void prefill(
    float* __restrict__ qk, float* __restrict__ v,
    __half* __restrict__ ah, __half* __restrict__ am,
    const float* __restrict__ qb, const float* __restrict__ kb,
    const float* __restrict__ vb)
{
    int idx = blockIdx.x * 256 + threadIdx.x;
    if (idx < 2097152) {
        size_t p = (size_t)idx * 4;
        int n = (int)(p & 2047);
        const float* bsrc = (n < D_) ? (qb + n) : (kb + n - D_);
        *(float4*)(qk + p) = *(const float4*)bsrc;
    } else if (idx < 2097152 + 1048576) {
        size_t p = (size_t)(idx - 2097152) * 4;
        int n = (int)(p & 1023);
        *(float4*)(v + p) = *(const float4*)(vb + n);
    } else if (idx < 2097152 + 1048576 + 8192) {
        int j = idx - (2097152 + 1048576);          // 0..8191
        int pl = j >> 12;                            // plane
        int r  = j & 4095;                           // 2 batches * 16 rows * 128 u4
        int b  = r >> 11;
        int rr = (r >> 7) & 15;
        int c  = r & 127;
        int row = (rr < 15) ? rr : (TPAD - 1);
        __half* dst = (pl ? am : ah) + ((size_t)b * TPAD + row) * D_ + c * 8;
        *(uint4*)dst = make_uint4(0u, 0u, 0u, 0u);
    }
}

// ---------------- HMMA GEMM core: one (tile, stage-range) segment ------------
// stage ls -> w = ls>>5, k0 = (ls&31)*32   (valid for conv, v and p tiles)
template<bool ATOMIC>
__device__ __forceinline__ void gemm_core(
    float* __restrict__ C,
    const __half* __restrict__ Ah, const __half* __restrict__ Am,
    const __half* __restrict__ Bh, const __half* __restrict__ Bm,
    const float* __restrict__ bias, int Ntot, int wbase,
    int m0, int n0, int ls0, int cnt)
{
    extern __shared__ __align__(1024) char smem[];
    const uint32_t sb = smem_u32(smem);
    const int tid = threadIdx.x, warp = tid >> 5, lane = tid & 31;
    const int wm = warp >> 2, wn = warp & 3;
    const int bb = m0 >> 11, t0 = m0 & (T_ - 1);
    const size_t arow0 = (size_t)bb * TPAD + t0 + wbase;

    auto load_stage = [&](int si) {
        const int ls = ls0 + si;
        const int w = ls >> 5, k0 = (ls & 31) * 32;
        const uint32_t st = sb + (si % NSTAGE) * STAGE_B;
        #pragma unroll
        for (int j = 0; j < 2; j++) {
            int idx = tid + j * 512;
            int c = idx & 3, row = (idx >> 2) & 127, pl = idx >> 9;
            const __half* src = (pl ? Am : Ah) + (arow0 + w + row) * D_ + k0 + c * 8;
            CP16(st + pl * A_PLANE + row * 80 + c * 16, src);
        }
        #pragma unroll
        for (int j = 0; j < 4; j++) {
            int idx = tid + j * 512;
            int c = idx & 3, row = (idx >> 2) & 255, pl = idx >> 10;
            const __half* src = (pl ? Bm : Bh)
                + ((size_t)w * Ntot + n0 + row) * (size_t)D_ + k0 + c * 8;
            CP16(st + 2 * A_PLANE + pl * B_PLANE + row * 80 + c * 16, src);
        }
        asm volatile("cp.async.commit_group;");
    };

    float acc[2][8][4];
    #pragma unroll
    for (int i = 0; i < 2; i++)
        #pragma unroll
        for (int j = 0; j < 8; j++)
            #pragma unroll
            for (int q = 0; q < 4; q++) acc[i][j][q] = 0.f;

    const int la = lane & 7, g1 = (lane >> 3) & 1, g2 = lane >> 4;
    const int arow_l = wm * 32 + g1 * 8 + la;
    const int brow_l = wn * 64 + g2 * 8 + la;

    __syncthreads();                 // protect smem reuse across segments
    load_stage(0);
    if (cnt > 1) load_stage(1);
    for (int s = 0; s < cnt; s++) {
        if (s + 1 < cnt) { asm volatile("cp.async.wait_group 1;" ::: "memory"); }
        else             { asm volatile("cp.async.wait_group 0;" ::: "memory"); }
        __syncthreads();
        if (s + 2 < cnt) load_stage(s + 2);

        const uint32_t st  = sb + (s % NSTAGE) * STAGE_B;
        const uint32_t Abh = st, Abm = st + A_PLANE;
        const uint32_t Bbh = st + 2 * A_PLANE, Bbm = Bbh + B_PLANE;
        #pragma unroll
        for (int kh = 0; kh < 2; kh++) {
            const int acol = kh * 32 + g2 * 16;
            const int bcol = kh * 32 + g1 * 16;
            uint32_t ah[2][4], am[2][4];
            #pragma unroll
            for (int mt = 0; mt < 2; mt++) {
                uint32_t off = (arow_l + mt * 16) * 80 + acol;
                ldsm4(ah[mt], Abh + off);
                ldsm4(am[mt], Abm + off);
            }
            #pragma unroll
            for (int ntp = 0; ntp < 4; ntp++) {
                uint32_t boff = (brow_l + ntp * 16) * 80 + bcol;
                uint32_t bh[4], bm[4];
                ldsm4(bh, Bbh + boff);
                ldsm4(bm, Bbm + boff);
                #pragma unroll
                for (int mt = 0; mt < 2; mt++) {
                    #pragma unroll
                    for (int hn = 0; hn < 2; hn++) {
                        float* a = acc[mt][ntp * 2 + hn];
                        mma16(a, ah[mt], bh + 2 * hn);
                        mma16(a, ah[mt], bm + 2 * hn);
                        mma16(a, am[mt], bh + 2 * hn);
                    }
                }
            }
        }
    }

    const int er = lane >> 2, ec = (lane & 3) * 2;
    #pragma unroll
    for (int mt = 0; mt < 2; mt++) {
        int row = m0 + wm * 32 + mt * 16 + er;
        #pragma unroll
        for (int nt = 0; nt < 8; nt++) {
            int col = n0 + wn * 64 + nt * 8 + ec;
            float* a = acc[mt][nt];
            if (ATOMIC) {
                float* c0 = &C[(size_t)row * Ntot + col];
                float* c1 = &C[(size_t)(row + 8) * Ntot + col];
                atomicAdd(c0,     a[0]); atomicAdd(c0 + 1, a[1]);
                atomicAdd(c1,     a[2]); atomicAdd(c1 + 1, a[3]);
            } else {
                float b0 = bias[col], b1 = bias[col + 1];
                *(float2*)&C[(size_t)row * Ntot + col] = make_float2(a[0] + b0, a[1] + b1);
                *(float2*)&C[(size_t)(row + 8) * Ntot + col] = make_float2(a[2] + b0, a[3] + b1);
            }
        }
    }
}

// stream-K: #SM CTAs walk contiguous ranges of the global stage stream
__global__ __launch_bounds__(512, 1) void gemm_streamk(
    float* __restrict__ qk, float* __restrict__ vout,
    const __half* __restrict__ Ah, const __half* __restrict__ Am,
    const __half* __restrict__ Bqh, const __half* __restrict__ Bqm,
    const __half* __restrict__ Bvh, const __half* __restrict__ Bvm,
    int ncta)
{
    int lo = (int)((long)blockIdx.x * G_STAGES / ncta);
    int hi = (int)((long)(blockIdx.x + 1) * G_STAGES / ncta);
    while (lo < hi) {
        int tile, tstart, tns;
        if (lo < CONV_STAGES) { tile = lo >> 9; tstart = tile << 9; tns = 512; }
        else {
            int o = lo - CONV_STAGES; int j = o >> 5;
            tile = 256 + j; tstart = CONV_STAGES + (j << 5); tns = 32;
        }
        int lsl = lo - tstart;
        int lsh = (hi - tstart < tns) ? (hi - tstart) : tns;

        float* C; const __half *Bh, *Bm; int Ntot, wb, m0, n0;
        if (tile < 256) {
            C = qk; Bh = Bqh; Bm = Bqm; Ntot = 2 * D_; wb = 0;
            m0 = (tile >> 3) * MT; n0 = (tile & 7) * NT;
        } else {
            int j = tile - 256;
            C = vout; Bh = Bvh; Bm = Bvm; Ntot = D_; wb = 15;
            m0 = (j >> 2) * MT; n0 = (j & 3) * NT;
        }
        gemm_core<true>(C, Ah, Am, Bh, Bm, nullptr, Ntot, wb, m0, n0, lsl, lsh - lsl);
        lo = tstart + lsh;
    }
}

// plain GEMM (p projection): bias in epilogue, plain stores
__global__ __launch_bounds__(512, 1) void gemm_hmma(
    float* __restrict__ C,
    const __half* __restrict__ Ah, const __half* __restrict__ Am,
    const __half* __restrict__ Bh, const __half* __restrict__ Bm,
    const float* __restrict__ bias)
{
    gemm_core<false>(C, Ah, Am, Bh, Bm, bias, D_, 15,
                     blockIdx.y * MT, blockIdx.x * NT, 0, 32);
}

// ---------------- log-sparse scores / stats ---------------------------------
__global__ __launch_bounds__(256) void e1_scores(
    const float* __restrict__ qk, float* __restrict__ scores)
{
    int lane = threadIdx.x & 31, wid = threadIdx.x >> 5;
    int gw = blockIdx.x * 8 + wid;
    int t = gw & (T_ - 1);
    int h = (gw >> 11) & 15;
    int b = gw >> 15;
    const float* qrow = qk + (size_t)(b * T_ + t) * 2048 + h * 64;
    float q0 = qrow[lane], q1 = qrow[lane + 32];
    #pragma unroll
    for (int e = 0; e < 8; e++) {
        int ts = (t + (1 << e)) & (T_ - 1);
        const float* kr = qk + (size_t)(b * T_ + ts) * 2048 + 1024 + h * 64;
        float s = q0 * kr[lane] + q1 * kr[lane + 32];
        #pragma unroll
        for (int o = 16; o; o >>= 1) s += __shfl_xor_sync(0xffffffffu, s, o);
        if (lane == 0)
            scores[((size_t)((b * 16 + h) * 8 + e)) * T_ + t] = s * 0.125f;
    }
}

__global__ void e2_stats(const float* __restrict__ scores, float2* __restrict__ stats)
{
    __shared__ float red[256];
    int idx = blockIdx.x;
    const float* s = scores + (size_t)idx * T_;
    int tid = threadIdx.x;
    float m = -1e30f;
    for (int i = tid; i < T_; i += 256) m = fmaxf(m, s[i]);
    red[tid] = m; __syncthreads();
    for (int o = 128; o > 0; o >>= 1) {
        if (tid < o) red[tid] = fmaxf(red[tid], red[tid + o]);
        __syncthreads();
    }
    float mt = red[0]; __syncthreads();
    float sm = 0.f;
    for (int i = tid; i < T_; i += 256) sm += expf(s[i] - mt);
    red[tid] = sm; __syncthreads();
    for (int o = 128; o > 0; o >>= 1) {
        if (tid < o) red[tid] += red[tid + o];
        __syncthreads();
    }
    if (tid == 0) stats[idx] = make_float2(mt, red[0]);
}

// ---------------- attention: writes fp16 h/m planes (padded) ----------------
__global__ __launch_bounds__(256) void attn_kernel(
    const float* __restrict__ qk, const float* __restrict__ vbuf,
    const float* __restrict__ scores, const float2* __restrict__ stats,
    __half* __restrict__ ah, __half* __restrict__ am)
{
    __shared__ float st[8][65];
    int lane = threadIdx.x & 31, wid = threadIdx.x >> 5;
    int tc = blockIdx.x & 255;
    int h  = (blockIdx.x >> 8) & 15;
    int b  = blockIdx.x >> 12;
    int t  = tc * 8 + wid;

    const float* qrow = qk + (size_t)(b * T_ + t) * 2048 + h * 64;
    float q0 = qrow[lane], q1 = qrow[lane + 32];

    float sw[16];
    #pragma unroll
    for (int w = 0; w < 16; w++) {
        int tt = t - 15 + w;
        float s = 0.f;
        if (tt >= 0) {
            const float* kr = qk + (size_t)(b * T_ + tt) * 2048 + 1024 + h * 64;
            s = q0 * kr[lane] + q1 * kr[lane + 32];
            #pragma unroll
            for (int o = 16; o; o >>= 1) s += __shfl_xor_sync(0xffffffffu, s, o);
            s *= 0.125f;
        }
        sw[w] = s;
    }
    float m = sw[0];
    #pragma unroll
    for (int w = 1; w < 16; w++) m = fmaxf(m, sw[w]);
    float den = 0.f;
    #pragma unroll
    for (int w = 0; w < 16; w++) den += expf(sw[w] - m);
    float inv = 1.f / den;

    float a0 = 0.f, a1 = 0.f;
    #pragma unroll
    for (int w = 0; w < 16; w++) {
        int tt = t - 15 + w;
        if (tt >= 0) {
            float al = expf(sw[w] - m) * inv;
            const float* vr = vbuf + (size_t)(b * T_ + tt) * 1024 + h * 64;
            a0 += al * vr[lane];
            a1 += al * vr[lane + 32];
        }
    }
    const float* sc = scores + ((size_t)((b * 16 + h) * 8)) * T_ + t;
    #pragma unroll
    for (int e = 0; e < 8; e++) {
        float2 stv = stats[(b * 16 + h) * 8 + e];
        float al = expf(sc[(size_t)e * T_] - stv.x) / stv.y;
        int ts = (t + (1 << e)) & (T_ - 1);
        const float* vr = vbuf + (size_t)(b * T_ + ts) * 1024 + h * 64;
        a0 += al * vr[lane];
        a1 += al * vr[lane + 32];
    }
    st[wid][lane]      = a0;
    st[wid][lane + 32] = a1;
    __syncthreads();
    for (int idx = threadIdx.x; idx < 512; idx += 256) {
        int d = idx >> 3, tt = idx & 7;
        float v = st[tt][d];
        __half hh = __float2half(v);
        __half mm = __float2half(v - __half2float(hh));
        size_t off = ((size_t)b * TPAD + 15 + tc * 8 + tt) * D_ + h * 64 + d;
        ah[off] = hh;
        am[off] = mm;
    }
}

// ---------------- launch ----------------------------------------------------
extern "C" void kernel_launch(void* const* d_in, const int* in_sizes, int n_in,
                              void* d_out, int out_size)
{
    const float* x   = (const float*)d_in[0];
    const float* q_w = (const float*)d_in[1];
    const float* q_b = (const float*)d_in[2];
    const float* k_w = (const float*)d_in[3];
    const float* k_b = (const float*)d_in[4];
    const float* v_w = (const float*)d_in[5];
    const float* v_b = (const float*)d_in[6];
    const float* p_w = (const float*)d_in[7];
    const float* p_b = (const float*)d_in[8];
    (void)in_sizes; (void)n_in; (void)out_size;

    void *xh, *xm, *wqkh, *wqkm, *wvh, *wvm, *wph, *wpm, *ah, *am;
    float *qk, *vbuf, *scores;
    float2* stats;
    cudaGetSymbolAddress(&xh, g_xh_);     cudaGetSymbolAddress(&xm, g_xm_);
    cudaGetSymbolAddress(&wqkh, g_wqkh_); cudaGetSymbolAddress(&wqkm, g_wqkm_);
    cudaGetSymbolAddress(&wvh, g_wvh_);   cudaGetSymbolAddress(&wvm, g_wvm_);
    cudaGetSymbolAddress(&wph, g_wph_);   cudaGetSymbolAddress(&wpm, g_wpm_);
    cudaGetSymbolAddress(&ah, g_ah_);     cudaGetSymbolAddress(&am, g_am_);
    cudaGetSymbolAddress((void**)&qk, g_qk);
    cudaGetSymbolAddress((void**)&vbuf, g_v);
    cudaGetSymbolAddress((void**)&scores, g_scores);
    cudaGetSymbolAddress((void**)&stats, g_stats);

    cudaFuncSetAttribute(gemm_streamk, cudaFuncAttributeMaxDynamicSharedMemorySize, SMEM_TOTAL);
    cudaFuncSetAttribute(gemm_hmma,    cudaFuncAttributeMaxDynamicSharedMemorySize, SMEM_TOTAL);

    int dev = 0, nsm = 148;
    cudaGetDevice(&dev);
    cudaDeviceGetAttribute(&nsm, cudaDevAttrMultiProcessorCount, dev);

    // 5 prep launches, so the stream-K GEMM is launch #6 (ncu -s 5 -c 1)
    prefill<<<(2097152 + 1048576 + 8192 + 255) / 256, 256>>>(
        qk, vbuf, (__half*)ah, (__half*)am, q_b, k_b, v_b);
    split_x<<<(int)((size_t)B_*TPAD*D_/256), 256>>>((__half*)xh, (__half*)xm, x);
    split_wqk<<<2*D_*16/8, 256>>>((__half*)wqkh, (__half*)wqkm, q_w, k_w);
    split_w1<<<D_*D_/256, 256>>>((__half*)wvh, (__half*)wvm, v_w);
    split_w1<<<D_*D_/256, 256>>>((__half*)wph, (__half*)wpm, p_w);

    // q+k causal conv + v projection, stream-K over 135168 stages, #SM CTAs
    gemm_streamk<<<nsm, 512, SMEM_TOTAL>>>(
        qk, vbuf, (const __half*)xh, (const __half*)xm,
        (const __half*)wqkh, (const __half*)wqkm,
        (const __half*)wvh, (const __half*)wvm, nsm);

    // attention
    e1_scores<<<B_*H_*T_/8, 256>>>(qk, scores);
    e2_stats<<<B_*H_*E_, 256>>>(scores, stats);
    attn_kernel<<<B_*H_*T_/8, 256>>>(qk, vbuf, scores, stats, (__half*)ah, (__half*)am);

    // output projection -> d_out
    gemm_hmma<<<dim3(D_/NT, BT_/MT), 512, SMEM_TOTAL>>>(
        (float*)d_out, (const __half*)ah, (const __half*)am,
        (const __half*)wph, (const __half*)wpm, p_b);
}